// round 3
// baseline (speedup 1.0000x reference)
#include <cuda_runtime.h>
#include <cstdint>

#define NB    4
#define NCATT 8
#define ND    48
#define NH    128
#define NW    256
#define NCF   80
#define NEMB  64
#define NHW   (NH*NW)          // 32768

// Scratch (device globals: allocation-free contract)
__device__ float g_Q[NB*NEMB*NHW];      // 33.5 MB
__device__ float g_K[NB*NEMB*NHW];
__device__ float g_V[NB*NEMB*NHW];
__device__ float g_delta[NB*NCATT*NHW]; // 16.8 MB

#define FMA2(d, a, b2) asm("fma.rn.f32x2 %0, %1, %2, %3;" : "=l"(d) : "l"(a), "l"(b2), "l"(d))
#define UNPACK2(lo, hi, d) asm("mov.b64 {%0, %1}, %2;" : "=f"(lo), "=f"(hi) : "l"(d))

// ---------------------------------------------------------------------------
// K1: QKV projection.  Out[192][n] = W[192][80] @ feat[80][n]  per batch.
// Warp-uniform weight operand: each warp owns 12 rows (uniform LDS ->
// broadcast, ~1 crossbar phase) x 128 block pixels (32 lanes x 4 px, natural
// f32x2 pairs, one lane-distinct LDS.128).  Crossbar drops below the fma-pipe
// demand -> kernel runs at the scalar-FFMA2 floor.
// ---------------------------------------------------------------------------
#define K1T  512               // 16 warps
#define NPB  128               // pixels per block
#define RPW  12                // rows per warp (16*12 = 192)
#define KT   40                // k-tile

__global__ __launch_bounds__(K1T, 1)
void qkv_proj_kernel(const float* __restrict__ feat,
                     const float* __restrict__ Wq,
                     const float* __restrict__ Wk,
                     const float* __restrict__ Wv) {
    extern __shared__ float smem1[];
    // wsh: [KT][192] duplicated pairs {w,w} (u64 each) = 61440 B
    unsigned long long* wsh = reinterpret_cast<unsigned long long*>(smem1);
    // fsh: [KT][128] natural floats = 20480 B
    float* fsh = smem1 + KT*192*2;

    const int b   = blockIdx.y;
    const int n0  = blockIdx.x * NPB;
    const int tid = threadIdx.x;
    const int w   = tid >> 5;          // warp 0..15 -> rows w*12..w*12+11
    const int l   = tid & 31;          // lane -> pixels l*4..l*4+3

    unsigned long long acc[RPW][2];
#pragma unroll
    for (int r = 0; r < RPW; r++) { acc[r][0] = 0ull; acc[r][1] = 0ull; }

    for (int kt = 0; kt < NCF; kt += KT) {
        // weights duplicated {w,w}
        for (int idx = tid; idx < KT*192; idx += K1T) {
            int k = idx / 192, e = idx - k*192;
            int kk = kt + k;
            float v;
            if (e < 64)       v = Wq[e*NCF + kk];
            else if (e < 128) v = Wk[(e-64)*NCF + kk];
            else              v = Wv[(e-128)*NCF + kk];
            float2 d2 = make_float2(v, v);
            wsh[idx] = *reinterpret_cast<unsigned long long*>(&d2);
        }
        // pixels natural
        for (int idx = tid; idx < KT*NPB; idx += K1T) {
            int k = idx >> 7, j = idx & 127;
            fsh[idx] = feat[(size_t)(b*NCF + kt + k)*NHW + n0 + j];
        }
        __syncthreads();

#pragma unroll 2
        for (int k = 0; k < KT; k++) {
            // 12 duplicated weight pairs, warp-uniform address -> broadcast
            const ulonglong2* wp =
                reinterpret_cast<const ulonglong2*>(&wsh[k*192 + w*RPW]);
            ulonglong2 w0 = wp[0], w1 = wp[1], w2 = wp[2],
                       w3 = wp[3], w4 = wp[4], w5 = wp[5];
            unsigned long long wd[RPW] = {w0.x,w0.y,w1.x,w1.y,w2.x,w2.y,
                                          w3.x,w3.y,w4.x,w4.y,w5.x,w5.y};
            // 4 pixels = 2 natural f32x2, one LDS.128
            ulonglong2 f =
                *reinterpret_cast<const ulonglong2*>(&fsh[k*NPB + l*4]);
#pragma unroll
            for (int r = 0; r < RPW; r++) {
                FMA2(acc[r][0], wd[r], f.x);
                FMA2(acc[r][1], wd[r], f.y);
            }
        }
        __syncthreads();
    }

#pragma unroll
    for (int r = 0; r < RPW; r++) {
        const int row = w*RPW + r;
        float* base = (row < 64) ? g_Q : ((row < 128) ? g_K : g_V);
        const int ch = row & 63;
        float a0, a1, a2, a3;
        UNPACK2(a0, a1, acc[r][0]);
        UNPACK2(a2, a3, acc[r][1]);
        *reinterpret_cast<float4*>(&base[(size_t)(b*NEMB + ch)*NHW + n0 + l*4]) =
            make_float4(a0, a1, a2, a3);
    }
}

// ---------------------------------------------------------------------------
// K2: local windowed MHA with the torch-unfold MIXED channel/window view.
// Channel dimension split into two 32-channel chunks -> 52KB smem -> 3
// blocks/SM.  Tile loader uses pointer-increment loops (no integer divides).
// ---------------------------------------------------------------------------
#define T2  128
#define TW  (T2+2)
#define EC  32                 // channels per chunk
#define CHUNK_F (EC*3*TW)      // floats per chunk tile

__device__ __forceinline__ void load_tile32(const float* __restrict__ src, float* sh,
                                            int b, int e0, int y, int x0, int tid) {
    const int gy0 = y - 1;
    const float* sb = src + (size_t)(b*NEMB + e0)*NHW + (size_t)gy0*NW + (x0 - 1);
    const int gx1 = x0 - 1 + tid;
    const bool ok1 = (unsigned)gx1 < NW;
    const int gx2 = x0 + 127 + tid;                 // tid<2 tail
    const bool ok2 = (unsigned)gx2 < NW;
    float* d = sh;
    for (int e = 0; e < EC; e++) {
        const float* se = sb + (size_t)e*NHW;
#pragma unroll
        for (int r = 0; r < 3; r++) {
            const bool rok = (unsigned)(gy0 + r) < NH;
            const float* sp = se + r*NW;
            d[tid] = (rok && ok1) ? sp[tid] : 0.0f;
            if (tid < 2) d[128 + tid] = (rok && ok2) ? sp[128 + tid] : 0.0f;
            d += TW;
        }
    }
}

template<int E0>
__device__ __forceinline__ void score_chunk(const float* sh, float (&sc)[36],
                                            const float (&Qr)[64], int tid) {
#pragma unroll
    for (int d = 0; d < 16; d++)
#pragma unroll
        for (int p = 0; p < 9; p++)
#pragma unroll
            for (int h = 0; h < 4; h++) {
                const int q = h*16 + d;
                const int L = p*64 + q;
                const int e = L/9, wi = L % 9;
                if (e >= E0 && e < E0 + EC) {
                    const int dyy = wi/3, dxx = wi % 3;
                    sc[h*9+p] += Qr[q] * sh[((e-E0)*3 + dyy)*TW + tid + dxx];
                }
            }
}

template<int E0>
__device__ __forceinline__ void ctx_chunk(const float* sh, float (&ctx)[64],
                                          const float (&sc)[36], int tid) {
#pragma unroll
    for (int p = 0; p < 9; p++)
#pragma unroll
        for (int d = 0; d < 16; d++)
#pragma unroll
            for (int h = 0; h < 4; h++) {
                const int q = h*16 + d;
                const int L = p*64 + q;
                const int e = L/9, wi = L % 9;
                if (e >= E0 && e < E0 + EC) {
                    const int dyy = wi/3, dxx = wi % 3;
                    ctx[q] += sc[h*9+p] * sh[((e-E0)*3 + dyy)*TW + tid + dxx];
                }
            }
}

__global__ __launch_bounds__(T2, 3)
void attn_kernel(const float* __restrict__ dispgap, const float* __restrict__ Wo) {
    extern __shared__ float smem2[];
    float* sh    = smem2;               // [32][3][130]
    float* wo_sh = smem2 + CHUNK_F;     // [8][64]
    const int b   = blockIdx.z;
    const int y   = blockIdx.y;
    const int x0  = blockIdx.x * T2;
    const int tid = threadIdx.x;
    const int x   = x0 + tid;

    for (int i = tid; i < NCATT*NEMB; i += T2) wo_sh[i] = Wo[i];
    load_tile32(g_K, sh, b, 0, y, x0, tid);

    float Qr[64];
#pragma unroll
    for (int e = 0; e < 64; e++)
        Qr[e] = g_Q[(size_t)(b*NEMB + e)*NHW + y*NW + x];

    float sc[36];
#pragma unroll
    for (int i = 0; i < 36; i++) sc[i] = 0.0f;

    __syncthreads();
    score_chunk<0>(sh, sc, Qr, tid);
    __syncthreads();
    load_tile32(g_K, sh, b, 32, y, x0, tid);
    __syncthreads();
    score_chunk<32>(sh, sc, Qr, tid);

    // Softmax over p (SCALE = 0.25 folded in)
#pragma unroll
    for (int h = 0; h < 4; h++) {
        float m = sc[h*9];
#pragma unroll
        for (int p = 1; p < 9; p++) m = fmaxf(m, sc[h*9+p]);
        float s = 0.0f;
#pragma unroll
        for (int p = 0; p < 9; p++) {
            float ev = __expf(0.25f*(sc[h*9+p] - m));
            sc[h*9+p] = ev;
            s += ev;
        }
        float inv = __fdividef(1.0f, s);
#pragma unroll
        for (int p = 0; p < 9; p++) sc[h*9+p] *= inv;
    }

    float ctx[64];
#pragma unroll
    for (int i = 0; i < 64; i++) ctx[i] = 0.0f;

    __syncthreads();
    load_tile32(g_V, sh, b, 0, y, x0, tid);
    __syncthreads();
    ctx_chunk<0>(sh, ctx, sc, tid);
    __syncthreads();
    load_tile32(g_V, sh, b, 32, y, x0, tid);
    __syncthreads();
    ctx_chunk<32>(sh, ctx, sc, tid);

    // Out-projection
    float outv[8];
#pragma unroll
    for (int a = 0; a < 8; a++) outv[a] = 0.0f;
#pragma unroll
    for (int q = 0; q < 64; q++)
#pragma unroll
        for (int a = 0; a < 8; a++)
            outv[a] += ctx[q] * wo_sh[a*64 + q];

    const float dg = dispgap[b*NHW + y*NW + x];
    const bool zero = (dg >= 2.0f);
#pragma unroll
    for (int a = 0; a < 8; a++)
        g_delta[((b*NCATT + a)*NH + y)*NW + x] = zero ? 0.0f : outv[a];
}

// ---------------------------------------------------------------------------
// K3: out[b,a,d,y,x] = attn_vol[b,a,d,y,x] + delta[b,a,y,x]   (float4,
// streaming hints so delta stays L2-resident)
// ---------------------------------------------------------------------------
__global__ void add_kernel(const float* __restrict__ attn, float* __restrict__ out) {
    int i4 = blockIdx.x * blockDim.x + threadIdx.x;     // exact grid, no tail
    float4 a = __ldcs(reinterpret_cast<const float4*>(attn) + i4);
    int inner = i4 & (NHW/4 - 1);
    int bad   = i4 >> 13;
    int ba    = bad / ND;
    float4 dl = __ldg(reinterpret_cast<const float4*>(g_delta) + ba*(NHW/4) + inner);
    a.x += dl.x; a.y += dl.y; a.z += dl.z; a.w += dl.w;
    __stcs(reinterpret_cast<float4*>(out) + i4, a);
}

// ---------------------------------------------------------------------------
extern "C" void kernel_launch(void* const* d_in, const int* in_sizes, int n_in,
                              void* d_out, int out_size) {
    const float* attn_vol = (const float*)d_in[0];
    const float* feat     = (const float*)d_in[1];
    const float* dispgap  = (const float*)d_in[2];
    const float* Wq       = (const float*)d_in[3];
    const float* Wk       = (const float*)d_in[4];
    const float* Wv       = (const float*)d_in[5];
    const float* Wo       = (const float*)d_in[6];
    float* out = (float*)d_out;

    const int smem1 = KT*192*8 + KT*NPB*4;              // 61440 + 20480 = 81920 B
    const int smem2 = (CHUNK_F + NCATT*NEMB) * 4;       // 49920 + 2048  = 51968 B
    cudaFuncSetAttribute(qkv_proj_kernel,
                         cudaFuncAttributeMaxDynamicSharedMemorySize, smem1);
    cudaFuncSetAttribute(attn_kernel,
                         cudaFuncAttributeMaxDynamicSharedMemorySize, smem2);

    qkv_proj_kernel<<<dim3(NHW/NPB, NB), K1T, smem1>>>(feat, Wq, Wk, Wv);
    attn_kernel<<<dim3(NW/T2, NH, NB), T2, smem2>>>(dispgap, Wo);
    add_kernel<<<(NB*NCATT*ND*NHW/4)/256, 256>>>(attn_vol, out);
}

// round 4
// speedup vs baseline: 1.6471x; 1.6471x over previous
#include <cuda_runtime.h>
#include <cstdint>

#define NB    4
#define NCATT 8
#define ND    48
#define NH    128
#define NW    256
#define NCF   80
#define NEMB  64
#define NHW   (NH*NW)          // 32768

// Scratch (device globals: allocation-free contract)
__device__ float g_Q[NB*NEMB*NHW];      // 33.5 MB
__device__ float g_K[NB*NEMB*NHW];
__device__ float g_V[NB*NEMB*NHW];
__device__ float g_delta[NB*NCATT*NHW]; // 16.8 MB

#define FMA2(d, a, b2) asm("fma.rn.f32x2 %0, %1, %2, %3;" : "=l"(d) : "l"(a), "l"(b2), "l"(d))
#define UNPACK2(lo, hi, d) asm("mov.b64 {%0, %1}, %2;" : "=f"(lo), "=f"(hi) : "l"(d))

// ---------------------------------------------------------------------------
// K1: QKV projection.  Out[192][n] = W[192][80] @ feat[80][n]  per batch.
// Warp-uniform weight operand (broadcast LDS), pixels as natural f32x2 pairs.
// RPW=6 keeps regs <=64 so 2 blocks (32 warps) fit per SM; rows split into
// two 96-row halves via blockIdx.y.
// ---------------------------------------------------------------------------
#define K1T  512               // 16 warps
#define NPB  128               // pixels per block
#define RPW  6                 // rows per warp (16*6 = 96 rows per block)
#define RPB  96                // rows per block
#define KT   40                // k-tile

__global__ __launch_bounds__(K1T, 2)
void qkv_proj_kernel(const float* __restrict__ feat,
                     const float* __restrict__ Wq,
                     const float* __restrict__ Wk,
                     const float* __restrict__ Wv) {
    extern __shared__ float smem1[];
    // wsh: [KT][96] duplicated pairs {w,w} (u64 each) = 30720 B
    unsigned long long* wsh = reinterpret_cast<unsigned long long*>(smem1);
    // fsh: [KT][128] natural floats = 20480 B
    float* fsh = smem1 + KT*RPB*2;

    const int half = blockIdx.y;       // 0: rows 0..95, 1: rows 96..191
    const int b    = blockIdx.z;
    const int n0   = blockIdx.x * NPB;
    const int tid  = threadIdx.x;
    const int w    = tid >> 5;         // warp 0..15 -> rows half*96 + w*6 ..
    const int l    = tid & 31;         // lane -> pixels l*4..l*4+3

    unsigned long long acc[RPW][2];
#pragma unroll
    for (int r = 0; r < RPW; r++) { acc[r][0] = 0ull; acc[r][1] = 0ull; }

    for (int kt = 0; kt < NCF; kt += KT) {
        // weights duplicated {w,w} for this block's 96 rows
        for (int idx = tid; idx < KT*RPB; idx += K1T) {
            int k = idx / RPB, el = idx - k*RPB;
            int e = half*RPB + el;
            int kk = kt + k;
            float v;
            if (e < 64)       v = Wq[e*NCF + kk];
            else if (e < 128) v = Wk[(e-64)*NCF + kk];
            else              v = Wv[(e-128)*NCF + kk];
            float2 d2 = make_float2(v, v);
            wsh[idx] = *reinterpret_cast<unsigned long long*>(&d2);
        }
        // pixels natural
        for (int idx = tid; idx < KT*NPB; idx += K1T) {
            int k = idx >> 7, j = idx & 127;
            fsh[idx] = feat[(size_t)(b*NCF + kt + k)*NHW + n0 + j];
        }
        __syncthreads();

#pragma unroll 2
        for (int k = 0; k < KT; k++) {
            // 6 duplicated weight pairs (48B), warp-uniform -> broadcast
            const ulonglong2* wp =
                reinterpret_cast<const ulonglong2*>(&wsh[k*RPB + w*RPW]);
            ulonglong2 w0 = wp[0], w1 = wp[1], w2 = wp[2];
            unsigned long long wd[RPW] = {w0.x, w0.y, w1.x, w1.y, w2.x, w2.y};
            // 4 pixels = 2 natural f32x2, one lane-distinct LDS.128
            ulonglong2 f =
                *reinterpret_cast<const ulonglong2*>(&fsh[k*NPB + l*4]);
#pragma unroll
            for (int r = 0; r < RPW; r++) {
                FMA2(acc[r][0], wd[r], f.x);
                FMA2(acc[r][1], wd[r], f.y);
            }
        }
        __syncthreads();
    }

#pragma unroll
    for (int r = 0; r < RPW; r++) {
        const int row = half*RPB + w*RPW + r;
        float* base = (row < 64) ? g_Q : ((row < 128) ? g_K : g_V);
        const int ch = row & 63;
        float a0, a1, a2, a3;
        UNPACK2(a0, a1, acc[r][0]);
        UNPACK2(a2, a3, acc[r][1]);
        *reinterpret_cast<float4*>(&base[(size_t)(b*NEMB + ch)*NHW + n0 + l*4]) =
            make_float4(a0, a1, a2, a3);
    }
}

// ---------------------------------------------------------------------------
// K2: local windowed MHA with the torch-unfold MIXED channel/window view.
// (REVERTED to the proven round-2 version.)  Channel dimension split into two
// 32-channel chunks -> 52KB smem -> 3 blocks/SM.
// ---------------------------------------------------------------------------
#define T2  128
#define TW  (T2+2)
#define EC  32                 // channels per chunk
#define CHUNK_F (EC*3*TW)      // floats per chunk tile

__device__ __forceinline__ void load_tile32(const float* __restrict__ src, float* sh,
                                            int b, int e0, int y, int x0, int tid) {
    for (int idx = tid; idx < CHUNK_F; idx += T2) {
        int e   = idx / (3*TW);
        int rem = idx - e*(3*TW);
        int r   = rem / TW;
        int xx  = rem - r*TW;
        int gy = y + r - 1;
        int gx = x0 + xx - 1;
        float v = 0.0f;
        if ((unsigned)gy < NH && (unsigned)gx < NW)
            v = src[(size_t)(b*NEMB + e0 + e)*NHW + gy*NW + gx];
        sh[idx] = v;
    }
}

template<int E0>
__device__ __forceinline__ void score_chunk(const float* sh, float (&sc)[36],
                                            const float (&Qr)[64], int tid) {
#pragma unroll
    for (int d = 0; d < 16; d++)
#pragma unroll
        for (int p = 0; p < 9; p++)
#pragma unroll
            for (int h = 0; h < 4; h++) {
                const int q = h*16 + d;
                const int L = p*64 + q;
                const int e = L/9, wi = L % 9;
                if (e >= E0 && e < E0 + EC) {
                    const int dyy = wi/3, dxx = wi % 3;
                    sc[h*9+p] += Qr[q] * sh[((e-E0)*3 + dyy)*TW + tid + dxx];
                }
            }
}

template<int E0>
__device__ __forceinline__ void ctx_chunk(const float* sh, float (&ctx)[64],
                                          const float (&sc)[36], int tid) {
#pragma unroll
    for (int p = 0; p < 9; p++)
#pragma unroll
        for (int d = 0; d < 16; d++)
#pragma unroll
            for (int h = 0; h < 4; h++) {
                const int q = h*16 + d;
                const int L = p*64 + q;
                const int e = L/9, wi = L % 9;
                if (e >= E0 && e < E0 + EC) {
                    const int dyy = wi/3, dxx = wi % 3;
                    ctx[q] += sc[h*9+p] * sh[((e-E0)*3 + dyy)*TW + tid + dxx];
                }
            }
}

__global__ __launch_bounds__(T2, 3)
void attn_kernel(const float* __restrict__ dispgap, const float* __restrict__ Wo) {
    extern __shared__ float smem2[];
    float* sh    = smem2;               // [32][3][130]
    float* wo_sh = smem2 + CHUNK_F;     // [8][64]
    const int b   = blockIdx.z;
    const int y   = blockIdx.y;
    const int x0  = blockIdx.x * T2;
    const int tid = threadIdx.x;
    const int x   = x0 + tid;

    for (int i = tid; i < NCATT*NEMB; i += T2) wo_sh[i] = Wo[i];
    load_tile32(g_K, sh, b, 0, y, x0, tid);

    float Qr[64];
#pragma unroll
    for (int e = 0; e < 64; e++)
        Qr[e] = g_Q[(size_t)(b*NEMB + e)*NHW + y*NW + x];

    float sc[36];
#pragma unroll
    for (int i = 0; i < 36; i++) sc[i] = 0.0f;

    __syncthreads();
    score_chunk<0>(sh, sc, Qr, tid);
    __syncthreads();
    load_tile32(g_K, sh, b, 32, y, x0, tid);
    __syncthreads();
    score_chunk<32>(sh, sc, Qr, tid);

    // Softmax over p (SCALE = 0.25 folded in)
#pragma unroll
    for (int h = 0; h < 4; h++) {
        float m = sc[h*9];
#pragma unroll
        for (int p = 1; p < 9; p++) m = fmaxf(m, sc[h*9+p]);
        float s = 0.0f;
#pragma unroll
        for (int p = 0; p < 9; p++) {
            float ev = __expf(0.25f*(sc[h*9+p] - m));
            sc[h*9+p] = ev;
            s += ev;
        }
        float inv = __fdividef(1.0f, s);
#pragma unroll
        for (int p = 0; p < 9; p++) sc[h*9+p] *= inv;
    }

    float ctx[64];
#pragma unroll
    for (int i = 0; i < 64; i++) ctx[i] = 0.0f;

    __syncthreads();
    load_tile32(g_V, sh, b, 0, y, x0, tid);
    __syncthreads();
    ctx_chunk<0>(sh, ctx, sc, tid);
    __syncthreads();
    load_tile32(g_V, sh, b, 32, y, x0, tid);
    __syncthreads();
    ctx_chunk<32>(sh, ctx, sc, tid);

    // Out-projection
    float outv[8];
#pragma unroll
    for (int a = 0; a < 8; a++) outv[a] = 0.0f;
#pragma unroll
    for (int q = 0; q < 64; q++)
#pragma unroll
        for (int a = 0; a < 8; a++)
            outv[a] += ctx[q] * wo_sh[a*64 + q];

    const float dg = dispgap[b*NHW + y*NW + x];
    const bool zero = (dg >= 2.0f);
#pragma unroll
    for (int a = 0; a < 8; a++)
        g_delta[((b*NCATT + a)*NH + y)*NW + x] = zero ? 0.0f : outv[a];
}

// ---------------------------------------------------------------------------
// K3: out[b,a,d,y,x] = attn_vol[b,a,d,y,x] + delta[b,a,y,x]   (float4,
// streaming hints so delta stays L2-resident)
// ---------------------------------------------------------------------------
__global__ void add_kernel(const float* __restrict__ attn, float* __restrict__ out) {
    int i4 = blockIdx.x * blockDim.x + threadIdx.x;     // exact grid, no tail
    float4 a = __ldcs(reinterpret_cast<const float4*>(attn) + i4);
    int inner = i4 & (NHW/4 - 1);
    int bad   = i4 >> 13;
    int ba    = bad / ND;
    float4 dl = __ldg(reinterpret_cast<const float4*>(g_delta) + ba*(NHW/4) + inner);
    a.x += dl.x; a.y += dl.y; a.z += dl.z; a.w += dl.w;
    __stcs(reinterpret_cast<float4*>(out) + i4, a);
}

// ---------------------------------------------------------------------------
extern "C" void kernel_launch(void* const* d_in, const int* in_sizes, int n_in,
                              void* d_out, int out_size) {
    const float* attn_vol = (const float*)d_in[0];
    const float* feat     = (const float*)d_in[1];
    const float* dispgap  = (const float*)d_in[2];
    const float* Wq       = (const float*)d_in[3];
    const float* Wk       = (const float*)d_in[4];
    const float* Wv       = (const float*)d_in[5];
    const float* Wo       = (const float*)d_in[6];
    float* out = (float*)d_out;

    const int smem1 = KT*RPB*8 + KT*NPB*4;              // 30720 + 20480 = 51200 B
    const int smem2 = (CHUNK_F + NCATT*NEMB) * 4;       // 49920 + 2048  = 51968 B
    cudaFuncSetAttribute(qkv_proj_kernel,
                         cudaFuncAttributeMaxDynamicSharedMemorySize, smem1);
    cudaFuncSetAttribute(attn_kernel,
                         cudaFuncAttributeMaxDynamicSharedMemorySize, smem2);

    qkv_proj_kernel<<<dim3(NHW/NPB, 2, NB), K1T, smem1>>>(feat, Wq, Wk, Wv);
    attn_kernel<<<dim3(NW/T2, NH, NB), T2, smem2>>>(dispgap, Wo);
    add_kernel<<<(NB*NCATT*ND*NHW/4)/256, 256>>>(attn_vol, out);
}

// round 5
// speedup vs baseline: 1.7878x; 1.0854x over previous
#include <cuda_runtime.h>
#include <cstdint>

#define NB    4
#define NCATT 8
#define ND    48
#define NH    128
#define NW    256
#define NCF   80
#define NEMB  64
#define NHW   (NH*NW)          // 32768

// Scratch (device globals: allocation-free contract)
__device__ float g_Q[NB*NEMB*NHW];      // 33.5 MB
__device__ float g_K[NB*NEMB*NHW];
__device__ float g_V[NB*NEMB*NHW];
__device__ float g_delta[NB*NCATT*NHW]; // 16.8 MB

#define FMA2(d, a, b2) asm("fma.rn.f32x2 %0, %1, %2, %3;" : "=l"(d) : "l"(a), "l"(b2), "l"(d))
#define UNPACK2(lo, hi, d) asm("mov.b64 {%0, %1}, %2;" : "=f"(lo), "=f"(hi) : "l"(d))

// ---------------------------------------------------------------------------
// K1: QKV projection (FROZEN from round 4: 156us, crossbar-bound).
// ---------------------------------------------------------------------------
#define K1T  512               // 16 warps
#define NPB  128               // pixels per block
#define RPW  6                 // rows per warp (16*6 = 96 rows per block)
#define RPB  96                // rows per block
#define KT   40                // k-tile

__global__ __launch_bounds__(K1T, 2)
void qkv_proj_kernel(const float* __restrict__ feat,
                     const float* __restrict__ Wq,
                     const float* __restrict__ Wk,
                     const float* __restrict__ Wv) {
    extern __shared__ float smem1[];
    unsigned long long* wsh = reinterpret_cast<unsigned long long*>(smem1);
    float* fsh = smem1 + KT*RPB*2;

    const int half = blockIdx.y;
    const int b    = blockIdx.z;
    const int n0   = blockIdx.x * NPB;
    const int tid  = threadIdx.x;
    const int w    = tid >> 5;
    const int l    = tid & 31;

    unsigned long long acc[RPW][2];
#pragma unroll
    for (int r = 0; r < RPW; r++) { acc[r][0] = 0ull; acc[r][1] = 0ull; }

    for (int kt = 0; kt < NCF; kt += KT) {
        for (int idx = tid; idx < KT*RPB; idx += K1T) {
            int k = idx / RPB, el = idx - k*RPB;
            int e = half*RPB + el;
            int kk = kt + k;
            float v;
            if (e < 64)       v = Wq[e*NCF + kk];
            else if (e < 128) v = Wk[(e-64)*NCF + kk];
            else              v = Wv[(e-128)*NCF + kk];
            float2 d2 = make_float2(v, v);
            wsh[idx] = *reinterpret_cast<unsigned long long*>(&d2);
        }
        for (int idx = tid; idx < KT*NPB; idx += K1T) {
            int k = idx >> 7, j = idx & 127;
            fsh[idx] = feat[(size_t)(b*NCF + kt + k)*NHW + n0 + j];
        }
        __syncthreads();

#pragma unroll 2
        for (int k = 0; k < KT; k++) {
            const ulonglong2* wp =
                reinterpret_cast<const ulonglong2*>(&wsh[k*RPB + w*RPW]);
            ulonglong2 w0 = wp[0], w1 = wp[1], w2 = wp[2];
            unsigned long long wd[RPW] = {w0.x, w0.y, w1.x, w1.y, w2.x, w2.y};
            ulonglong2 f =
                *reinterpret_cast<const ulonglong2*>(&fsh[k*NPB + l*4]);
#pragma unroll
            for (int r = 0; r < RPW; r++) {
                FMA2(acc[r][0], wd[r], f.x);
                FMA2(acc[r][1], wd[r], f.y);
            }
        }
        __syncthreads();
    }

#pragma unroll
    for (int r = 0; r < RPW; r++) {
        const int row = half*RPB + w*RPW + r;
        float* base = (row < 64) ? g_Q : ((row < 128) ? g_K : g_V);
        const int ch = row & 63;
        float a0, a1, a2, a3;
        UNPACK2(a0, a1, acc[r][0]);
        UNPACK2(a2, a3, acc[r][1]);
        *reinterpret_cast<float4*>(&base[(size_t)(b*NEMB + ch)*NHW + n0 + l*4]) =
            make_float4(a0, a1, a2, a3);
    }
}

// ---------------------------------------------------------------------------
// K2: local windowed MHA.  Same structure as the proven round-2 version; the
// ONLY change is the tile loader: div-free incremental (e,r,xx) walk with
// pointer arithmetic (divides were serializing LDG address generation).
// ---------------------------------------------------------------------------
#define T2  128
#define TW  (T2+2)
#define EC  32                 // channels per chunk
#define CHUNK_F (EC*3*TW)      // floats per chunk tile = 12480

__device__ __forceinline__ void load_tile32(const float* __restrict__ src, float* sh,
                                            int b, int e0, int y, int x0, int tid) {
    // idx = tid + i*T2 decomposed as (e, r, xx): idx = e*(3*TW) + r*TW + xx.
    // tid < 128 < TW  ->  start at e=0, r=0, xx=tid.
    int xx = tid;
    int r  = 0;
    const float* p = src + (size_t)(b*NEMB + e0)*NHW
                         + (size_t)(y-1)*NW + (x0 - 1) + tid;
    const bool ylo = (y == 0);
    const bool yhi = (y == NH-1);
#pragma unroll 6
    for (int idx = tid; idx < CHUNK_F; idx += T2) {
        bool ok = !((r == 0 && ylo) || (r == 2 && yhi));
        int gx = x0 - 1 + xx;
        if ((unsigned)gx >= NW) ok = false;
        sh[idx] = ok ? __ldg(p) : 0.0f;
        // advance by T2: single xx-wrap (stride 128 < TW=130), then r-wrap
        xx += T2; p += T2;
        if (xx >= TW) { xx -= TW; r++; p += NW - TW; }
        if (r >= 3)   { r -= 3;       p += NHW - 3*NW; }
    }
}

template<int E0>
__device__ __forceinline__ void score_chunk(const float* sh, float (&sc)[36],
                                            const float (&Qr)[64], int tid) {
#pragma unroll
    for (int d = 0; d < 16; d++)
#pragma unroll
        for (int p = 0; p < 9; p++)
#pragma unroll
            for (int h = 0; h < 4; h++) {
                const int q = h*16 + d;
                const int L = p*64 + q;
                const int e = L/9, wi = L % 9;
                if (e >= E0 && e < E0 + EC) {
                    const int dyy = wi/3, dxx = wi % 3;
                    sc[h*9+p] += Qr[q] * sh[((e-E0)*3 + dyy)*TW + tid + dxx];
                }
            }
}

template<int E0>
__device__ __forceinline__ void ctx_chunk(const float* sh, float (&ctx)[64],
                                          const float (&sc)[36], int tid) {
#pragma unroll
    for (int p = 0; p < 9; p++)
#pragma unroll
        for (int d = 0; d < 16; d++)
#pragma unroll
            for (int h = 0; h < 4; h++) {
                const int q = h*16 + d;
                const int L = p*64 + q;
                const int e = L/9, wi = L % 9;
                if (e >= E0 && e < E0 + EC) {
                    const int dyy = wi/3, dxx = wi % 3;
                    ctx[q] += sc[h*9+p] * sh[((e-E0)*3 + dyy)*TW + tid + dxx];
                }
            }
}

__global__ __launch_bounds__(T2, 3)
void attn_kernel(const float* __restrict__ dispgap, const float* __restrict__ Wo) {
    extern __shared__ float smem2[];
    float* sh    = smem2;               // [32][3][130]
    float* wo_sh = smem2 + CHUNK_F;     // [8][64]
    const int b   = blockIdx.z;
    const int y   = blockIdx.y;
    const int x0  = blockIdx.x * T2;
    const int tid = threadIdx.x;
    const int x   = x0 + tid;

    for (int i = tid; i < NCATT*NEMB; i += T2) wo_sh[i] = Wo[i];
    load_tile32(g_K, sh, b, 0, y, x0, tid);

    float Qr[64];
#pragma unroll
    for (int e = 0; e < 64; e++)
        Qr[e] = g_Q[(size_t)(b*NEMB + e)*NHW + y*NW + x];

    float sc[36];
#pragma unroll
    for (int i = 0; i < 36; i++) sc[i] = 0.0f;

    __syncthreads();
    score_chunk<0>(sh, sc, Qr, tid);
    __syncthreads();
    load_tile32(g_K, sh, b, 32, y, x0, tid);
    __syncthreads();
    score_chunk<32>(sh, sc, Qr, tid);

    // Softmax over p (SCALE = 0.25 folded in)
#pragma unroll
    for (int h = 0; h < 4; h++) {
        float m = sc[h*9];
#pragma unroll
        for (int p = 1; p < 9; p++) m = fmaxf(m, sc[h*9+p]);
        float s = 0.0f;
#pragma unroll
        for (int p = 0; p < 9; p++) {
            float ev = __expf(0.25f*(sc[h*9+p] - m));
            sc[h*9+p] = ev;
            s += ev;
        }
        float inv = __fdividef(1.0f, s);
#pragma unroll
        for (int p = 0; p < 9; p++) sc[h*9+p] *= inv;
    }

    float ctx[64];
#pragma unroll
    for (int i = 0; i < 64; i++) ctx[i] = 0.0f;

    __syncthreads();
    load_tile32(g_V, sh, b, 0, y, x0, tid);
    __syncthreads();
    ctx_chunk<0>(sh, ctx, sc, tid);
    __syncthreads();
    load_tile32(g_V, sh, b, 32, y, x0, tid);
    __syncthreads();
    ctx_chunk<32>(sh, ctx, sc, tid);

    // Out-projection
    float outv[8];
#pragma unroll
    for (int a = 0; a < 8; a++) outv[a] = 0.0f;
#pragma unroll
    for (int q = 0; q < 64; q++)
#pragma unroll
        for (int a = 0; a < 8; a++)
            outv[a] += ctx[q] * wo_sh[a*64 + q];

    const float dg = dispgap[b*NHW + y*NW + x];
    const bool zero = (dg >= 2.0f);
#pragma unroll
    for (int a = 0; a < 8; a++)
        g_delta[((b*NCATT + a)*NH + y)*NW + x] = zero ? 0.0f : outv[a];
}

// ---------------------------------------------------------------------------
// K3: out[b,a,d,y,x] = attn_vol[b,a,d,y,x] + delta[b,a,y,x]
// ---------------------------------------------------------------------------
__global__ void add_kernel(const float* __restrict__ attn, float* __restrict__ out) {
    int i4 = blockIdx.x * blockDim.x + threadIdx.x;     // exact grid, no tail
    float4 a = __ldcs(reinterpret_cast<const float4*>(attn) + i4);
    int inner = i4 & (NHW/4 - 1);
    int bad   = i4 >> 13;
    int ba    = bad / ND;
    float4 dl = __ldg(reinterpret_cast<const float4*>(g_delta) + ba*(NHW/4) + inner);
    a.x += dl.x; a.y += dl.y; a.z += dl.z; a.w += dl.w;
    __stcs(reinterpret_cast<float4*>(out) + i4, a);
}

// ---------------------------------------------------------------------------
extern "C" void kernel_launch(void* const* d_in, const int* in_sizes, int n_in,
                              void* d_out, int out_size) {
    const float* attn_vol = (const float*)d_in[0];
    const float* feat     = (const float*)d_in[1];
    const float* dispgap  = (const float*)d_in[2];
    const float* Wq       = (const float*)d_in[3];
    const float* Wk       = (const float*)d_in[4];
    const float* Wv       = (const float*)d_in[5];
    const float* Wo       = (const float*)d_in[6];
    float* out = (float*)d_out;

    const int smem1 = KT*RPB*8 + KT*NPB*4;              // 51200 B
    const int smem2 = (CHUNK_F + NCATT*NEMB) * 4;       // 51968 B
    cudaFuncSetAttribute(qkv_proj_kernel,
                         cudaFuncAttributeMaxDynamicSharedMemorySize, smem1);
    cudaFuncSetAttribute(attn_kernel,
                         cudaFuncAttributeMaxDynamicSharedMemorySize, smem2);

    qkv_proj_kernel<<<dim3(NHW/NPB, 2, NB), K1T, smem1>>>(feat, Wq, Wk, Wv);
    attn_kernel<<<dim3(NW/T2, NH, NB), T2, smem2>>>(dispgap, Wo);
    add_kernel<<<(NB*NCATT*ND*NHW/4)/256, 256>>>(attn_vol, out);
}

// round 7
// speedup vs baseline: 2.4086x; 1.3473x over previous
#include <cuda_runtime.h>
#include <cstdint>

#define NB    4
#define NCATT 8
#define ND    48
#define NH    128
#define NW    256
#define NCF   80
#define NEMB  64
#define NHW   (NH*NW)          // 32768

// Scratch (device globals: allocation-free contract)
__device__ float g_Q[NB*NEMB*NHW];      // 33.5 MB
__device__ float g_K[NB*NEMB*NHW];
__device__ float g_V[NB*NEMB*NHW];
__device__ float g_delta[NB*NCATT*NHW]; // 16.8 MB
// Weight fragments, tf32-rounded, laid out exactly as m16n8k8 B-operand frags:
// [kstep s 0..9][e-tile t 0..23][lane 0..31][{b0,b1}]
__device__ float g_Wfrag[10*24*32*2];

// ---------------------------------------------------------------------------
// K0: build tf32-rounded B-operand fragment image (tiny, one block).
// B[k][e] = W[e][k];  frag: b0 = B[s*8 + l%4][t*8 + l/4], b1 = same k+4.
// ---------------------------------------------------------------------------
__global__ void wfrag_kernel(const float* __restrict__ Wq,
                             const float* __restrict__ Wk,
                             const float* __restrict__ Wv) {
    for (int idx = threadIdx.x; idx < 10*24*32*2; idx += blockDim.x) {
        int j  = idx & 1;
        int pi = idx >> 1;
        int l  = pi & 31;
        int tt = pi >> 5;
        int t  = tt % 24, s = tt / 24;
        int e  = t*8 + (l >> 2);
        int k  = s*8 + (l & 3) + j*4;          // 0..79, exact cover
        float wv;
        if (e < 64)       wv = Wq[e*NCF + k];
        else if (e < 128) wv = Wk[(e-64)*NCF + k];
        else              wv = Wv[(e-128)*NCF + k];
        uint32_t r;
        asm("cvt.rna.tf32.f32 %0, %1;" : "=r"(r) : "f"(wv));
        g_Wfrag[idx] = __uint_as_float(r);
    }
}

// ---------------------------------------------------------------------------
// K1: QKV projection via mma.sync tf32 (baseline sm_80+ PTX, no 'a' features).
// Per CTA: 128 px x 192 e, K=80.  8 warps: warp = 2 M-tiles(32px) x 12
// N-tiles(96e).  A = feat [k][px+pad] smem (cp.async row copy); B = g_Wfrag
// straight copy.  D frags stored directly to g_Q/K/V (32B sectors, full use).
// ---------------------------------------------------------------------------
#define APAD   132
#define A_BYTES (80*APAD*4)        // 42240
#define B_BYTES (10*24*32*2*4)     // 61440
#define SMEM1  (A_BYTES + B_BYTES) // 103680

__device__ __forceinline__ uint32_t smem_u32(const void* p) {
    uint32_t a;
    asm("{ .reg .u64 t; cvta.to.shared.u64 t, %1; cvt.u32.u64 %0, t; }"
        : "=r"(a) : "l"(p));
    return a;
}
__device__ __forceinline__ void mma_tf32(float* c, const uint32_t* a,
                                         const uint32_t* b) {
    asm("mma.sync.aligned.m16n8k8.row.col.f32.tf32.tf32.f32 "
        "{%0,%1,%2,%3}, {%4,%5,%6,%7}, {%8,%9}, {%0,%1,%2,%3};"
        : "+f"(c[0]), "+f"(c[1]), "+f"(c[2]), "+f"(c[3])
        : "r"(a[0]), "r"(a[1]), "r"(a[2]), "r"(a[3]), "r"(b[0]), "r"(b[1]));
}
__device__ __forceinline__ uint32_t to_tf32(float v) {
    uint32_t r;
    asm("cvt.rna.tf32.f32 %0, %1;" : "=r"(r) : "f"(v));
    return r;
}

__global__ __launch_bounds__(256)
void qkv_mma_kernel(const float* __restrict__ feat) {
    extern __shared__ float sm[];
    float* shA = sm;                    // [80][132]
    float* shB = sm + 80*APAD;          // frag image
    const int tid  = threadIdx.x;
    const int lane = tid & 31;
    const int wid  = tid >> 5;
    const int b    = blockIdx.x >> 8;
    const int n0   = (blockIdx.x & 255) << 7;
    const uint32_t sbase = smem_u32(sm);

    // --- fills via cp.async (pure copies) ---
    {
        const float* srcA = feat + (size_t)b*NCF*NHW + n0;
        for (int idx = tid; idx < 2560; idx += 256) {       // 80 rows x 32 16B
            int k = idx >> 5, c = idx & 31;
            uint32_t dst = sbase + (uint32_t)(k*APAD + c*4)*4;
            const float* s = srcA + (size_t)k*NHW + c*4;
            asm volatile("cp.async.ca.shared.global [%0], [%1], 16;"
                         :: "r"(dst), "l"(s));
        }
        const uint32_t bb = sbase + A_BYTES;
        const float4* srcB = reinterpret_cast<const float4*>(g_Wfrag);
        for (int idx = tid; idx < 3840; idx += 256) {       // 61440/16
            asm volatile("cp.async.ca.shared.global [%0], [%1], 16;"
                         :: "r"(bb + idx*16), "l"(srcB + idx));
        }
        asm volatile("cp.async.commit_group;");
        asm volatile("cp.async.wait_group 0;");
    }
    __syncthreads();

    const int pxg = wid & 3;            // 4 pixel groups of 32
    const int eh  = wid >> 2;           // 2 e-halves of 96
    const int px0 = pxg*32;
    const int l4  = lane >> 2, lm4 = lane & 3;

    float acc[2][12][4];
#pragma unroll
    for (int m = 0; m < 2; m++)
#pragma unroll
        for (int t = 0; t < 12; t++)
#pragma unroll
            for (int j = 0; j < 4; j++) acc[m][t][j] = 0.0f;

    const float* aBase = shA + lm4*APAD + px0 + l4;
    const float* bBase = shB + eh*12*64 + lane*2;

#pragma unroll
    for (int s = 0; s < 10; s++) {
        uint32_t A[2][4];
#pragma unroll
        for (int m = 0; m < 2; m++) {
            const float* ap = aBase + s*8*APAD + m*16;
            A[m][0] = to_tf32(ap[0]);
            A[m][1] = to_tf32(ap[8]);
            A[m][2] = to_tf32(ap[4*APAD]);
            A[m][3] = to_tf32(ap[4*APAD + 8]);
        }
        uint32_t B[12][2];
#pragma unroll
        for (int t = 0; t < 12; t++) {
            float2 bv = *reinterpret_cast<const float2*>(bBase + (s*24 + t)*64);
            B[t][0] = __float_as_uint(bv.x);
            B[t][1] = __float_as_uint(bv.y);
        }
#pragma unroll
        for (int m = 0; m < 2; m++)
#pragma unroll
            for (int t = 0; t < 12; t++)
                mma_tf32(acc[m][t], A[m], B[t]);
    }

    // --- store D frags directly (8-px 32B sectors, fully utilized) ---
#pragma unroll
    for (int t = 0; t < 12; t++) {
        const int e0 = (eh*12 + t)*8 + lm4*2;      // even, e0+1 same segment
        float* seg = (e0 < 64) ? g_Q : ((e0 < 128) ? g_K : g_V);
        const int ch0 = e0 & 63;
        float* d0 = seg + (size_t)(b*NEMB + ch0)*NHW + n0 + px0 + l4;
        float* d1 = d0 + NHW;
#pragma unroll
        for (int m = 0; m < 2; m++) {
            d0[m*16]     = acc[m][t][0];
            d1[m*16]     = acc[m][t][1];
            d0[m*16 + 8] = acc[m][t][2];
            d1[m*16 + 8] = acc[m][t][3];
        }
    }
}

// ---------------------------------------------------------------------------
// K2: local windowed MHA (FROZEN from round 5, 376.8us config).
// ---------------------------------------------------------------------------
#define T2  128
#define TW  (T2+2)
#define EC  32
#define CHUNK_F (EC*3*TW)

__device__ __forceinline__ void load_tile32(const float* __restrict__ src, float* sh,
                                            int b, int e0, int y, int x0, int tid) {
    int xx = tid;
    int r  = 0;
    const float* p = src + (size_t)(b*NEMB + e0)*NHW
                         + (size_t)(y-1)*NW + (x0 - 1) + tid;
    const bool ylo = (y == 0);
    const bool yhi = (y == NH-1);
#pragma unroll 6
    for (int idx = tid; idx < CHUNK_F; idx += T2) {
        bool ok = !((r == 0 && ylo) || (r == 2 && yhi));
        int gx = x0 - 1 + xx;
        if ((unsigned)gx >= NW) ok = false;
        sh[idx] = ok ? __ldg(p) : 0.0f;
        xx += T2; p += T2;
        if (xx >= TW) { xx -= TW; r++; p += NW - TW; }
        if (r >= 3)   { r -= 3;       p += NHW - 3*NW; }
    }
}

template<int E0>
__device__ __forceinline__ void score_chunk(const float* sh, float (&sc)[36],
                                            const float (&Qr)[64], int tid) {
#pragma unroll
    for (int d = 0; d < 16; d++)
#pragma unroll
        for (int p = 0; p < 9; p++)
#pragma unroll
            for (int h = 0; h < 4; h++) {
                const int q = h*16 + d;
                const int L = p*64 + q;
                const int e = L/9, wi = L % 9;
                if (e >= E0 && e < E0 + EC) {
                    const int dyy = wi/3, dxx = wi % 3;
                    sc[h*9+p] += Qr[q] * sh[((e-E0)*3 + dyy)*TW + tid + dxx];
                }
            }
}

template<int E0>
__device__ __forceinline__ void ctx_chunk(const float* sh, float (&ctx)[64],
                                          const float (&sc)[36], int tid) {
#pragma unroll
    for (int p = 0; p < 9; p++)
#pragma unroll
        for (int d = 0; d < 16; d++)
#pragma unroll
            for (int h = 0; h < 4; h++) {
                const int q = h*16 + d;
                const int L = p*64 + q;
                const int e = L/9, wi = L % 9;
                if (e >= E0 && e < E0 + EC) {
                    const int dyy = wi/3, dxx = wi % 3;
                    ctx[q] += sc[h*9+p] * sh[((e-E0)*3 + dyy)*TW + tid + dxx];
                }
            }
}

__global__ __launch_bounds__(T2, 3)
void attn_kernel(const float* __restrict__ dispgap, const float* __restrict__ Wo) {
    extern __shared__ float smem2[];
    float* sh    = smem2;
    float* wo_sh = smem2 + CHUNK_F;
    const int b   = blockIdx.z;
    const int y   = blockIdx.y;
    const int x0  = blockIdx.x * T2;
    const int tid = threadIdx.x;
    const int x   = x0 + tid;

    for (int i = tid; i < NCATT*NEMB; i += T2) wo_sh[i] = Wo[i];
    load_tile32(g_K, sh, b, 0, y, x0, tid);

    float Qr[64];
#pragma unroll
    for (int e = 0; e < 64; e++)
        Qr[e] = g_Q[(size_t)(b*NEMB + e)*NHW + y*NW + x];

    float sc[36];
#pragma unroll
    for (int i = 0; i < 36; i++) sc[i] = 0.0f;

    __syncthreads();
    score_chunk<0>(sh, sc, Qr, tid);
    __syncthreads();
    load_tile32(g_K, sh, b, 32, y, x0, tid);
    __syncthreads();
    score_chunk<32>(sh, sc, Qr, tid);

#pragma unroll
    for (int h = 0; h < 4; h++) {
        float m = sc[h*9];
#pragma unroll
        for (int p = 1; p < 9; p++) m = fmaxf(m, sc[h*9+p]);
        float s = 0.0f;
#pragma unroll
        for (int p = 0; p < 9; p++) {
            float ev = __expf(0.25f*(sc[h*9+p] - m));
            sc[h*9+p] = ev;
            s += ev;
        }
        float inv = __fdividef(1.0f, s);
#pragma unroll
        for (int p = 0; p < 9; p++) sc[h*9+p] *= inv;
    }

    float ctx[64];
#pragma unroll
    for (int i = 0; i < 64; i++) ctx[i] = 0.0f;

    __syncthreads();
    load_tile32(g_V, sh, b, 0, y, x0, tid);
    __syncthreads();
    ctx_chunk<0>(sh, ctx, sc, tid);
    __syncthreads();
    load_tile32(g_V, sh, b, 32, y, x0, tid);
    __syncthreads();
    ctx_chunk<32>(sh, ctx, sc, tid);

    float outv[8];
#pragma unroll
    for (int a = 0; a < 8; a++) outv[a] = 0.0f;
#pragma unroll
    for (int q = 0; q < 64; q++)
#pragma unroll
        for (int a = 0; a < 8; a++)
            outv[a] += ctx[q] * wo_sh[a*64 + q];

    const float dg = dispgap[b*NHW + y*NW + x];
    const bool zero = (dg >= 2.0f);
#pragma unroll
    for (int a = 0; a < 8; a++)
        g_delta[((b*NCATT + a)*NH + y)*NW + x] = zero ? 0.0f : outv[a];
}

// ---------------------------------------------------------------------------
// K3: broadcast add (FROZEN).
// ---------------------------------------------------------------------------
__global__ void add_kernel(const float* __restrict__ attn, float* __restrict__ out) {
    int i4 = blockIdx.x * blockDim.x + threadIdx.x;
    float4 a = __ldcs(reinterpret_cast<const float4*>(attn) + i4);
    int inner = i4 & (NHW/4 - 1);
    int bad   = i4 >> 13;
    int ba    = bad / ND;
    float4 dl = __ldg(reinterpret_cast<const float4*>(g_delta) + ba*(NHW/4) + inner);
    a.x += dl.x; a.y += dl.y; a.z += dl.z; a.w += dl.w;
    __stcs(reinterpret_cast<float4*>(out) + i4, a);
}

// ---------------------------------------------------------------------------
extern "C" void kernel_launch(void* const* d_in, const int* in_sizes, int n_in,
                              void* d_out, int out_size) {
    const float* attn_vol = (const float*)d_in[0];
    const float* feat     = (const float*)d_in[1];
    const float* dispgap  = (const float*)d_in[2];
    const float* Wq       = (const float*)d_in[3];
    const float* Wk       = (const float*)d_in[4];
    const float* Wv       = (const float*)d_in[5];
    const float* Wo       = (const float*)d_in[6];
    float* out = (float*)d_out;

    const int smem2 = (CHUNK_F + NCATT*NEMB) * 4;
    cudaFuncSetAttribute(qkv_mma_kernel,
                         cudaFuncAttributeMaxDynamicSharedMemorySize, SMEM1);
    cudaFuncSetAttribute(attn_kernel,
                         cudaFuncAttributeMaxDynamicSharedMemorySize, smem2);

    wfrag_kernel<<<1, 512>>>(Wq, Wk, Wv);
    qkv_mma_kernel<<<NB*256, 256, SMEM1>>>(feat);
    attn_kernel<<<dim3(NW/T2, NH, NB), T2, smem2>>>(dispgap, Wo);
    add_kernel<<<(NB*NCATT*ND*NHW/4)/256, 256>>>(attn_vol, out);
}

// round 13
// speedup vs baseline: 3.6003x; 1.4948x over previous
#include <cuda_runtime.h>
#include <cstdint>

#define NB    4
#define NCATT 8
#define ND    48
#define NH    128
#define NW    256
#define NCF   80
#define NEMB  64
#define NHW   (NH*NW)          // 32768

// Scratch (device globals: allocation-free contract)
__device__ float g_Q[NB*NEMB*NHW];      // 33.5 MB
__device__ float g_K[NB*NEMB*NHW];
__device__ float g_V[NB*NEMB*NHW];
__device__ float g_delta[NB*NCATT*NHW]; // 16.8 MB
// Weight fragments, tf32-rounded, m16n8k8 B-operand layout
__device__ float g_Wfrag[10*24*32*2];

__device__ __forceinline__ uint32_t smem_u32(const void* p) {
    uint32_t a;
    asm("{ .reg .u64 t; cvta.to.shared.u64 t, %1; cvt.u32.u64 %0, t; }"
        : "=r"(a) : "l"(p));
    return a;
}

// ---------------------------------------------------------------------------
// K0: tf32-rounded B-operand fragment image (FROZEN).
// ---------------------------------------------------------------------------
__global__ void wfrag_kernel(const float* __restrict__ Wq,
                             const float* __restrict__ Wk,
                             const float* __restrict__ Wv) {
    for (int idx = threadIdx.x; idx < 10*24*32*2; idx += blockDim.x) {
        int j  = idx & 1;
        int pi = idx >> 1;
        int l  = pi & 31;
        int tt = pi >> 5;
        int t  = tt % 24, s = tt / 24;
        int e  = t*8 + (l >> 2);
        int k  = s*8 + (l & 3) + j*4;
        float wv;
        if (e < 64)       wv = Wq[e*NCF + k];
        else if (e < 128) wv = Wk[(e-64)*NCF + k];
        else              wv = Wv[(e-128)*NCF + k];
        uint32_t r;
        asm("cvt.rna.tf32.f32 %0, %1;" : "=r"(r) : "f"(wv));
        g_Wfrag[idx] = __uint_as_float(r);
    }
}

// ---------------------------------------------------------------------------
// K1: QKV projection via mma.sync tf32 (FROZEN from round 7).
// ---------------------------------------------------------------------------
#define APAD   132
#define A_BYTES (80*APAD*4)
#define B_BYTES (10*24*32*2*4)
#define SMEM1  (A_BYTES + B_BYTES)

__device__ __forceinline__ void mma_tf32(float* c, const uint32_t* a,
                                         const uint32_t* b) {
    asm("mma.sync.aligned.m16n8k8.row.col.f32.tf32.tf32.f32 "
        "{%0,%1,%2,%3}, {%4,%5,%6,%7}, {%8,%9}, {%0,%1,%2,%3};"
        : "+f"(c[0]), "+f"(c[1]), "+f"(c[2]), "+f"(c[3])
        : "r"(a[0]), "r"(a[1]), "r"(a[2]), "r"(a[3]), "r"(b[0]), "r"(b[1]));
}
__device__ __forceinline__ uint32_t to_tf32(float v) {
    uint32_t r;
    asm("cvt.rna.tf32.f32 %0, %1;" : "=r"(r) : "f"(v));
    return r;
}

__global__ __launch_bounds__(256)
void qkv_mma_kernel(const float* __restrict__ feat) {
    extern __shared__ float sm[];
    float* shA = sm;
    float* shB = sm + 80*APAD;
    const int tid  = threadIdx.x;
    const int lane = tid & 31;
    const int wid  = tid >> 5;
    const int b    = blockIdx.x >> 8;
    const int n0   = (blockIdx.x & 255) << 7;
    const uint32_t sbase = smem_u32(sm);

    {
        const float* srcA = feat + (size_t)b*NCF*NHW + n0;
        for (int idx = tid; idx < 2560; idx += 256) {
            int k = idx >> 5, c = idx & 31;
            uint32_t dst = sbase + (uint32_t)(k*APAD + c*4)*4;
            const float* s = srcA + (size_t)k*NHW + c*4;
            asm volatile("cp.async.ca.shared.global [%0], [%1], 16;"
                         :: "r"(dst), "l"(s));
        }
        const uint32_t bb = sbase + A_BYTES;
        const float4* srcB = reinterpret_cast<const float4*>(g_Wfrag);
        for (int idx = tid; idx < 3840; idx += 256) {
            asm volatile("cp.async.ca.shared.global [%0], [%1], 16;"
                         :: "r"(bb + idx*16), "l"(srcB + idx));
        }
        asm volatile("cp.async.commit_group;");
        asm volatile("cp.async.wait_group 0;");
    }
    __syncthreads();

    const int pxg = wid & 3;
    const int eh  = wid >> 2;
    const int px0 = pxg*32;
    const int l4  = lane >> 2, lm4 = lane & 3;

    float acc[2][12][4];
#pragma unroll
    for (int m = 0; m < 2; m++)
#pragma unroll
        for (int t = 0; t < 12; t++)
#pragma unroll
            for (int j = 0; j < 4; j++) acc[m][t][j] = 0.0f;

    const float* aBase = shA + lm4*APAD + px0 + l4;
    const float* bBase = shB + eh*12*64 + lane*2;

#pragma unroll
    for (int s = 0; s < 10; s++) {
        uint32_t A[2][4];
#pragma unroll
        for (int m = 0; m < 2; m++) {
            const float* ap = aBase + s*8*APAD + m*16;
            A[m][0] = to_tf32(ap[0]);
            A[m][1] = to_tf32(ap[8]);
            A[m][2] = to_tf32(ap[4*APAD]);
            A[m][3] = to_tf32(ap[4*APAD + 8]);
        }
        uint32_t B[12][2];
#pragma unroll
        for (int t = 0; t < 12; t++) {
            float2 bv = *reinterpret_cast<const float2*>(bBase + (s*24 + t)*64);
            B[t][0] = __float_as_uint(bv.x);
            B[t][1] = __float_as_uint(bv.y);
        }
#pragma unroll
        for (int m = 0; m < 2; m++)
#pragma unroll
            for (int t = 0; t < 12; t++)
                mma_tf32(acc[m][t], A[m], B[t]);
    }

#pragma unroll
    for (int t = 0; t < 12; t++) {
        const int e0 = (eh*12 + t)*8 + lm4*2;
        float* seg = (e0 < 64) ? g_Q : ((e0 < 128) ? g_K : g_V);
        const int ch0 = e0 & 63;
        float* d0 = seg + (size_t)(b*NEMB + ch0)*NHW + n0 + px0 + l4;
        float* d1 = d0 + NHW;
#pragma unroll
        for (int m = 0; m < 2; m++) {
            d0[m*16]     = acc[m][t][0];
            d1[m*16]     = acc[m][t][1];
            d0[m*16 + 8] = acc[m][t][2];
            d1[m*16 + 8] = acc[m][t][3];
        }
    }
}

// ---------------------------------------------------------------------------
// K2: local windowed MHA.  2 y-rows x 128 px per block (256 thr).  8 segments
// of 16 channels (K:4, V:4), double-buffered cp.async.
// FIX vs round 7/11: seg_load source now includes the channel offset ch*NHW
// (was loading channel e0 for all 16 channels of a segment).
// ---------------------------------------------------------------------------
#define SEG_CH   16
#define ROW_F    136                       // floats per smem row
#define SEG_F    (SEG_CH*4*ROW_F)          // 8704 floats = 34816 B
#define NCHUNK   (SEG_CH*4*34)             // 2176 16B chunks per segment

__device__ __forceinline__ void seg_load(float* buf, const float* __restrict__ src,
                                         int b, int e0, int y0, int x0, int tid) {
    const float* sb = src + (size_t)(b*NEMB + e0)*NHW;
#pragma unroll
    for (int i = 0; i < 9; i++) {
        const int idx = tid + i*256;
        if (i < 8 || idx < NCHUNK) {
            const int c34 = idx % 34;
            const int t4  = idx / 34;
            const int rr  = t4 & 3;
            const int ch  = t4 >> 2;
            const int gy  = y0 - 1 + rr;
            const int gxs = x0 - 4 + c34*4;
            float* d = buf + ch*544 + rr*ROW_F + c34*4;
            const bool ok = ((unsigned)gy < NH) & ((unsigned)gxs < (NW-3));
            if (ok) {
                const float* s = sb + (size_t)ch*NHW + (size_t)gy*NW + gxs;
                asm volatile("cp.async.ca.shared.global [%0], [%1], 16;"
                             :: "r"(smem_u32(d)), "l"(s));
            } else {
                *reinterpret_cast<float4*>(d) = make_float4(0.f,0.f,0.f,0.f);
            }
        }
    }
}
#define CP_COMMIT() asm volatile("cp.async.commit_group;" ::: "memory")
#define CP_WAIT1()  asm volatile("cp.async.wait_group 1;" ::: "memory")
#define CP_WAIT0()  asm volatile("cp.async.wait_group 0;" ::: "memory")

template<int E0>
__device__ __forceinline__ void score_seg(const float* sh, float (&sc)[36],
                                          const float (&Qr)[64], int bx) {
#pragma unroll
    for (int d = 0; d < 16; d++)
#pragma unroll
        for (int p = 0; p < 9; p++)
#pragma unroll
            for (int h = 0; h < 4; h++) {
                const int q = h*16 + d;
                const int L = p*64 + q;
                const int e = L/9, wi = L % 9;
                if (e >= E0 && e < E0 + SEG_CH) {
                    const int dyy = wi/3, dxx = wi % 3;
                    sc[h*9+p] += Qr[q] * sh[(e-E0)*544 + dyy*ROW_F + dxx + bx];
                }
            }
}

template<int E0>
__device__ __forceinline__ void ctx_seg(const float* sh, float (&ctx)[64],
                                        const float (&sc)[36], int bx) {
#pragma unroll
    for (int p = 0; p < 9; p++)
#pragma unroll
        for (int d = 0; d < 16; d++)
#pragma unroll
            for (int h = 0; h < 4; h++) {
                const int q = h*16 + d;
                const int L = p*64 + q;
                const int e = L/9, wi = L % 9;
                if (e >= E0 && e < E0 + SEG_CH) {
                    const int dyy = wi/3, dxx = wi % 3;
                    ctx[q] += sc[h*9+p] * sh[(e-E0)*544 + dyy*ROW_F + dxx + bx];
                }
            }
}

__global__ __launch_bounds__(256, 2)
void attn_kernel(const float* __restrict__ dispgap, const float* __restrict__ Wo) {
    extern __shared__ float smem2[];
    float* B0    = smem2;
    float* B1    = smem2 + SEG_F;
    float* wo_sh = smem2 + 2*SEG_F;
    const int b   = blockIdx.z;
    const int y0  = blockIdx.y * 2;
    const int x0  = blockIdx.x * 128;
    const int tid = threadIdx.x;
    const int x   = tid & 127;
    const int yy  = tid >> 7;
    const int bx  = yy*ROW_F + x + 4 - 1;      // col 3 maps to gx = x0-1

    for (int i = tid; i < NCATT*NEMB; i += 256) wo_sh[i] = Wo[i];

    seg_load(B0, g_K, b, 0,  y0, x0, tid);  CP_COMMIT();
    seg_load(B1, g_K, b, 16, y0, x0, tid);  CP_COMMIT();

    float Qr[64];
#pragma unroll
    for (int e = 0; e < 64; e++)
        Qr[e] = g_Q[(size_t)(b*NEMB + e)*NHW + (y0+yy)*NW + x0 + x];

    float sc[36];
#pragma unroll
    for (int i = 0; i < 36; i++) sc[i] = 0.0f;

    // seg 0
    CP_WAIT1(); __syncthreads();
    score_seg<0>(B0, sc, Qr, bx);
    __syncthreads();
    seg_load(B0, g_K, b, 32, y0, x0, tid);  CP_COMMIT();
    // seg 1
    CP_WAIT1(); __syncthreads();
    score_seg<16>(B1, sc, Qr, bx);
    __syncthreads();
    seg_load(B1, g_K, b, 48, y0, x0, tid);  CP_COMMIT();
    // seg 2
    CP_WAIT1(); __syncthreads();
    score_seg<32>(B0, sc, Qr, bx);
    __syncthreads();
    seg_load(B0, g_V, b, 0,  y0, x0, tid);  CP_COMMIT();
    // seg 3
    CP_WAIT1(); __syncthreads();
    score_seg<48>(B1, sc, Qr, bx);

    // softmax over p (SCALE = 0.25 folded in)
#pragma unroll
    for (int h = 0; h < 4; h++) {
        float m = sc[h*9];
#pragma unroll
        for (int p = 1; p < 9; p++) m = fmaxf(m, sc[h*9+p]);
        float s = 0.0f;
#pragma unroll
        for (int p = 0; p < 9; p++) {
            float ev = __expf(0.25f*(sc[h*9+p] - m));
            sc[h*9+p] = ev;
            s += ev;
        }
        float inv = __fdividef(1.0f, s);
#pragma unroll
        for (int p = 0; p < 9; p++) sc[h*9+p] *= inv;
    }
    __syncthreads();
    seg_load(B1, g_V, b, 16, y0, x0, tid);  CP_COMMIT();

    float ctx[64];
#pragma unroll
    for (int i = 0; i < 64; i++) ctx[i] = 0.0f;

    // seg 4
    CP_WAIT1(); __syncthreads();
    ctx_seg<0>(B0, ctx, sc, bx);
    __syncthreads();
    seg_load(B0, g_V, b, 32, y0, x0, tid);  CP_COMMIT();
    // seg 5
    CP_WAIT1(); __syncthreads();
    ctx_seg<16>(B1, ctx, sc, bx);
    __syncthreads();
    seg_load(B1, g_V, b, 48, y0, x0, tid);  CP_COMMIT();
    // seg 6
    CP_WAIT1(); __syncthreads();
    ctx_seg<32>(B0, ctx, sc, bx);
    // seg 7
    CP_WAIT0(); __syncthreads();
    ctx_seg<48>(B1, ctx, sc, bx);

    // out-projection (wo_sh reads are warp-uniform -> broadcast)
    float outv[8];
#pragma unroll
    for (int a = 0; a < 8; a++) outv[a] = 0.0f;
#pragma unroll
    for (int q = 0; q < 64; q++)
#pragma unroll
        for (int a = 0; a < 8; a++)
            outv[a] += ctx[q] * wo_sh[a*64 + q];

    const int gy = y0 + yy;
    const float dg = dispgap[b*NHW + gy*NW + x0 + x];
    const bool zero = (dg >= 2.0f);
#pragma unroll
    for (int a = 0; a < 8; a++)
        g_delta[((b*NCATT + a)*NH + gy)*NW + x0 + x] = zero ? 0.0f : outv[a];
}

// ---------------------------------------------------------------------------
// K3: broadcast add (FROZEN — 74% DRAM, at roofline).
// ---------------------------------------------------------------------------
__global__ void add_kernel(const float* __restrict__ attn, float* __restrict__ out) {
    int i4 = blockIdx.x * blockDim.x + threadIdx.x;
    float4 a = __ldcs(reinterpret_cast<const float4*>(attn) + i4);
    int inner = i4 & (NHW/4 - 1);
    int bad   = i4 >> 13;
    int ba    = bad / ND;
    float4 dl = __ldg(reinterpret_cast<const float4*>(g_delta) + ba*(NHW/4) + inner);
    a.x += dl.x; a.y += dl.y; a.z += dl.z; a.w += dl.w;
    __stcs(reinterpret_cast<float4*>(out) + i4, a);
}

// ---------------------------------------------------------------------------
extern "C" void kernel_launch(void* const* d_in, const int* in_sizes, int n_in,
                              void* d_out, int out_size) {
    const float* attn_vol = (const float*)d_in[0];
    const float* feat     = (const float*)d_in[1];
    const float* dispgap  = (const float*)d_in[2];
    const float* Wq       = (const float*)d_in[3];
    const float* Wk       = (const float*)d_in[4];
    const float* Wv       = (const float*)d_in[5];
    const float* Wo       = (const float*)d_in[6];
    float* out = (float*)d_out;

    const int smem2 = (2*SEG_F + NCATT*NEMB) * 4;   // 69632 + 2048 = 71680 B
    cudaFuncSetAttribute(qkv_mma_kernel,
                         cudaFuncAttributeMaxDynamicSharedMemorySize, SMEM1);
    cudaFuncSetAttribute(attn_kernel,
                         cudaFuncAttributeMaxDynamicSharedMemorySize, smem2);

    wfrag_kernel<<<1, 512>>>(Wq, Wk, Wv);
    qkv_mma_kernel<<<NB*256, 256, SMEM1>>>(feat);
    attn_kernel<<<dim3(2, 64, NB), 256, smem2>>>(dispgap, Wo);
    add_kernel<<<(NB*NCATT*ND*NHW/4)/256, 256>>>(attn_vol, out);
}

// round 14
// speedup vs baseline: 3.6420x; 1.0116x over previous
#include <cuda_runtime.h>
#include <cstdint>

#define NB    4
#define NCATT 8
#define ND    48
#define NH    128
#define NW    256
#define NCF   80
#define NEMB  64
#define NHW   (NH*NW)          // 32768

// Scratch (device globals: allocation-free contract)
__device__ float g_Q[NB*NEMB*NHW];      // 33.5 MB
__device__ float g_K[NB*NEMB*NHW];
__device__ float g_V[NB*NEMB*NHW];
__device__ float g_delta[NB*NCATT*NHW]; // 16.8 MB
// Weight fragments, tf32-rounded, m16n8k8 B-operand layout
__device__ float g_Wfrag[10*24*32*2];

__device__ __forceinline__ uint32_t smem_u32(const void* p) {
    uint32_t a;
    asm("{ .reg .u64 t; cvta.to.shared.u64 t, %1; cvt.u32.u64 %0, t; }"
        : "=r"(a) : "l"(p));
    return a;
}

// ---------------------------------------------------------------------------
// K0: tf32-rounded B-operand fragment image (FROZEN).
// ---------------------------------------------------------------------------
__global__ void wfrag_kernel(const float* __restrict__ Wq,
                             const float* __restrict__ Wk,
                             const float* __restrict__ Wv) {
    for (int idx = threadIdx.x; idx < 10*24*32*2; idx += blockDim.x) {
        int j  = idx & 1;
        int pi = idx >> 1;
        int l  = pi & 31;
        int tt = pi >> 5;
        int t  = tt % 24, s = tt / 24;
        int e  = t*8 + (l >> 2);
        int k  = s*8 + (l & 3) + j*4;
        float wv;
        if (e < 64)       wv = Wq[e*NCF + k];
        else if (e < 128) wv = Wk[(e-64)*NCF + k];
        else              wv = Wv[(e-128)*NCF + k];
        uint32_t r;
        asm("cvt.rna.tf32.f32 %0, %1;" : "=r"(r) : "f"(wv));
        g_Wfrag[idx] = __uint_as_float(r);
    }
}

// ---------------------------------------------------------------------------
// K1: QKV projection via mma.sync tf32 — PERSISTENT CTA version.
// 148 CTAs loop over 1024 (b,n0) tiles.  B fragments resident in smem
// (loaded once per CTA); A tiles double-buffered via cp.async so the fill of
// tile i+1 overlaps the MMA of tile i.  512 thr: warp = 16px M-tile x 12
// N-tiles (eh half), acc 48 regs.
// ---------------------------------------------------------------------------
#define APAD    132
#define A_FLOAT (80*APAD)          // floats per A buffer
#define A_BYTES (A_FLOAT*4)        // 42240
#define B_BYTES (10*24*32*2*4)     // 61440
#define SMEM1   (2*A_BYTES + B_BYTES)   // 145920
#define NTILES  (NB*256)           // 1024

__device__ __forceinline__ void mma_tf32(float* c, const uint32_t* a,
                                         const uint32_t* b) {
    asm("mma.sync.aligned.m16n8k8.row.col.f32.tf32.tf32.f32 "
        "{%0,%1,%2,%3}, {%4,%5,%6,%7}, {%8,%9}, {%0,%1,%2,%3};"
        : "+f"(c[0]), "+f"(c[1]), "+f"(c[2]), "+f"(c[3])
        : "r"(a[0]), "r"(a[1]), "r"(a[2]), "r"(a[3]), "r"(b[0]), "r"(b[1]));
}
__device__ __forceinline__ uint32_t to_tf32(float v) {
    uint32_t r;
    asm("cvt.rna.tf32.f32 %0, %1;" : "=r"(r) : "f"(v));
    return r;
}
#define CPA16(dst, src) \
    asm volatile("cp.async.ca.shared.global [%0], [%1], 16;" \
                 :: "r"(dst), "l"(src))
#define CP_COMMIT() asm volatile("cp.async.commit_group;" ::: "memory")
#define CP_WAIT1()  asm volatile("cp.async.wait_group 1;" ::: "memory")
#define CP_WAIT0()  asm volatile("cp.async.wait_group 0;" ::: "memory")

__device__ __forceinline__ void a_load(uint32_t dstA, const float* __restrict__ feat,
                                       int tile, int tid) {
    const int b  = tile >> 8;
    const int n0 = (tile & 255) << 7;
    const float* srcA = feat + (size_t)b*NCF*NHW + n0;
#pragma unroll
    for (int i = 0; i < 5; i++) {                 // 2560 chunks / 512 thr
        const int idx = tid + i*512;
        const int k = idx >> 5, c = idx & 31;
        CPA16(dstA + (uint32_t)(k*APAD + c*4)*4, srcA + (size_t)k*NHW + c*4);
    }
}

__global__ __launch_bounds__(512, 1)
void qkv_mma_kernel(const float* __restrict__ feat) {
    extern __shared__ float sm[];
    float* shA[2] = { sm, sm + A_FLOAT };
    float* shB    = sm + 2*A_FLOAT;
    const int tid  = threadIdx.x;
    const int lane = tid & 31;
    const int wid  = tid >> 5;
    const uint32_t sbase = smem_u32(sm);
    const uint32_t aAddr[2] = { sbase, sbase + A_BYTES };

    // --- B resident load (once) + first A tile, one group ---
    {
        const uint32_t bb = sbase + 2*A_BYTES;
        const float4* srcB = reinterpret_cast<const float4*>(g_Wfrag);
        for (int idx = tid; idx < 3840; idx += 512)
            CPA16(bb + idx*16, srcB + idx);
        if ((int)blockIdx.x < NTILES)
            a_load(aAddr[0], feat, blockIdx.x, tid);
        CP_COMMIT();
    }

    const int pxg = wid & 7;            // 8 groups of 16 px
    const int eh  = wid >> 3;           // 2 e-halves of 96
    const int px0 = pxg*16;
    const int l4  = lane >> 2, lm4 = lane & 3;
    const float* bBase = shB + eh*12*64 + lane*2;

    int i = 0;
    for (int tile = blockIdx.x; tile < NTILES; tile += gridDim.x, i++) {
        const int cur = i & 1;
        const int nxt = cur ^ 1;
        __syncthreads();                 // everyone done reading shA[nxt]
        const int ntile = tile + gridDim.x;
        if (ntile < NTILES) a_load(aAddr[nxt], feat, ntile, tid);
        CP_COMMIT();
        CP_WAIT1();                      // A(tile) + B complete
        __syncthreads();

        const float* curA = shA[cur];
        float acc[12][4];
#pragma unroll
        for (int t = 0; t < 12; t++)
#pragma unroll
            for (int j = 0; j < 4; j++) acc[t][j] = 0.0f;

        const float* aBase = curA + lm4*APAD + px0 + l4;
#pragma unroll
        for (int s = 0; s < 10; s++) {
            const float* ap = aBase + s*8*APAD;
            uint32_t A[4];
            A[0] = to_tf32(ap[0]);
            A[1] = to_tf32(ap[8]);
            A[2] = to_tf32(ap[4*APAD]);
            A[3] = to_tf32(ap[4*APAD + 8]);
            uint32_t B[12][2];
#pragma unroll
            for (int t = 0; t < 12; t++) {
                float2 bv = *reinterpret_cast<const float2*>(bBase + (s*24 + t)*64);
                B[t][0] = __float_as_uint(bv.x);
                B[t][1] = __float_as_uint(bv.y);
            }
#pragma unroll
            for (int t = 0; t < 12; t++)
                mma_tf32(acc[t], A, B[t]);
        }

        const int b  = tile >> 8;
        const int n0 = (tile & 255) << 7;
#pragma unroll
        for (int t = 0; t < 12; t++) {
            const int e0 = (eh*12 + t)*8 + lm4*2;
            float* seg = (e0 < 64) ? g_Q : ((e0 < 128) ? g_K : g_V);
            const int ch0 = e0 & 63;
            float* d0 = seg + (size_t)(b*NEMB + ch0)*NHW + n0 + px0 + l4;
            float* d1 = d0 + NHW;
            d0[0] = acc[t][0];
            d1[0] = acc[t][1];
            d0[8] = acc[t][2];
            d1[8] = acc[t][3];
        }
    }
}

// ---------------------------------------------------------------------------
// K2: local windowed MHA (FROZEN from round 13: 2-row blocks, double-buffered
// cp.async segments).
// ---------------------------------------------------------------------------
#define SEG_CH   16
#define ROW_F    136                       // floats per smem row
#define SEG_F    (SEG_CH*4*ROW_F)          // 8704 floats = 34816 B
#define NCHUNK   (SEG_CH*4*34)             // 2176 16B chunks per segment

__device__ __forceinline__ void seg_load(float* buf, const float* __restrict__ src,
                                         int b, int e0, int y0, int x0, int tid) {
    const float* sb = src + (size_t)(b*NEMB + e0)*NHW;
#pragma unroll
    for (int i = 0; i < 9; i++) {
        const int idx = tid + i*256;
        if (i < 8 || idx < NCHUNK) {
            const int c34 = idx % 34;
            const int t4  = idx / 34;
            const int rr  = t4 & 3;
            const int ch  = t4 >> 2;
            const int gy  = y0 - 1 + rr;
            const int gxs = x0 - 4 + c34*4;
            float* d = buf + ch*544 + rr*ROW_F + c34*4;
            const bool ok = ((unsigned)gy < NH) & ((unsigned)gxs < (NW-3));
            if (ok) {
                const float* s = sb + (size_t)ch*NHW + (size_t)gy*NW + gxs;
                asm volatile("cp.async.ca.shared.global [%0], [%1], 16;"
                             :: "r"(smem_u32(d)), "l"(s));
            } else {
                *reinterpret_cast<float4*>(d) = make_float4(0.f,0.f,0.f,0.f);
            }
        }
    }
}

template<int E0>
__device__ __forceinline__ void score_seg(const float* sh, float (&sc)[36],
                                          const float (&Qr)[64], int bx) {
#pragma unroll
    for (int d = 0; d < 16; d++)
#pragma unroll
        for (int p = 0; p < 9; p++)
#pragma unroll
            for (int h = 0; h < 4; h++) {
                const int q = h*16 + d;
                const int L = p*64 + q;
                const int e = L/9, wi = L % 9;
                if (e >= E0 && e < E0 + SEG_CH) {
                    const int dyy = wi/3, dxx = wi % 3;
                    sc[h*9+p] += Qr[q] * sh[(e-E0)*544 + dyy*ROW_F + dxx + bx];
                }
            }
}

template<int E0>
__device__ __forceinline__ void ctx_seg(const float* sh, float (&ctx)[64],
                                        const float (&sc)[36], int bx) {
#pragma unroll
    for (int p = 0; p < 9; p++)
#pragma unroll
        for (int d = 0; d < 16; d++)
#pragma unroll
            for (int h = 0; h < 4; h++) {
                const int q = h*16 + d;
                const int L = p*64 + q;
                const int e = L/9, wi = L % 9;
                if (e >= E0 && e < E0 + SEG_CH) {
                    const int dyy = wi/3, dxx = wi % 3;
                    ctx[q] += sc[h*9+p] * sh[(e-E0)*544 + dyy*ROW_F + dxx + bx];
                }
            }
}

__global__ __launch_bounds__(256, 2)
void attn_kernel(const float* __restrict__ dispgap, const float* __restrict__ Wo) {
    extern __shared__ float smem2[];
    float* B0    = smem2;
    float* B1    = smem2 + SEG_F;
    float* wo_sh = smem2 + 2*SEG_F;
    const int b   = blockIdx.z;
    const int y0  = blockIdx.y * 2;
    const int x0  = blockIdx.x * 128;
    const int tid = threadIdx.x;
    const int x   = tid & 127;
    const int yy  = tid >> 7;
    const int bx  = yy*ROW_F + x + 4 - 1;      // col 3 maps to gx = x0-1

    for (int i = tid; i < NCATT*NEMB; i += 256) wo_sh[i] = Wo[i];

    seg_load(B0, g_K, b, 0,  y0, x0, tid);  CP_COMMIT();
    seg_load(B1, g_K, b, 16, y0, x0, tid);  CP_COMMIT();

    float Qr[64];
#pragma unroll
    for (int e = 0; e < 64; e++)
        Qr[e] = g_Q[(size_t)(b*NEMB + e)*NHW + (y0+yy)*NW + x0 + x];

    float sc[36];
#pragma unroll
    for (int i = 0; i < 36; i++) sc[i] = 0.0f;

    // seg 0
    CP_WAIT1(); __syncthreads();
    score_seg<0>(B0, sc, Qr, bx);
    __syncthreads();
    seg_load(B0, g_K, b, 32, y0, x0, tid);  CP_COMMIT();
    // seg 1
    CP_WAIT1(); __syncthreads();
    score_seg<16>(B1, sc, Qr, bx);
    __syncthreads();
    seg_load(B1, g_K, b, 48, y0, x0, tid);  CP_COMMIT();
    // seg 2
    CP_WAIT1(); __syncthreads();
    score_seg<32>(B0, sc, Qr, bx);
    __syncthreads();
    seg_load(B0, g_V, b, 0,  y0, x0, tid);  CP_COMMIT();
    // seg 3
    CP_WAIT1(); __syncthreads();
    score_seg<48>(B1, sc, Qr, bx);

    // softmax over p (SCALE = 0.25 folded in)
#pragma unroll
    for (int h = 0; h < 4; h++) {
        float m = sc[h*9];
#pragma unroll
        for (int p = 1; p < 9; p++) m = fmaxf(m, sc[h*9+p]);
        float s = 0.0f;
#pragma unroll
        for (int p = 0; p < 9; p++) {
            float ev = __expf(0.25f*(sc[h*9+p] - m));
            sc[h*9+p] = ev;
            s += ev;
        }
        float inv = __fdividef(1.0f, s);
#pragma unroll
        for (int p = 0; p < 9; p++) sc[h*9+p] *= inv;
    }
    __syncthreads();
    seg_load(B1, g_V, b, 16, y0, x0, tid);  CP_COMMIT();

    float ctx[64];
#pragma unroll
    for (int i = 0; i < 64; i++) ctx[i] = 0.0f;

    // seg 4
    CP_WAIT1(); __syncthreads();
    ctx_seg<0>(B0, ctx, sc, bx);
    __syncthreads();
    seg_load(B0, g_V, b, 32, y0, x0, tid);  CP_COMMIT();
    // seg 5
    CP_WAIT1(); __syncthreads();
    ctx_seg<16>(B1, ctx, sc, bx);
    __syncthreads();
    seg_load(B1, g_V, b, 48, y0, x0, tid);  CP_COMMIT();
    // seg 6
    CP_WAIT1(); __syncthreads();
    ctx_seg<32>(B0, ctx, sc, bx);
    // seg 7
    CP_WAIT0(); __syncthreads();
    ctx_seg<48>(B1, ctx, sc, bx);

    // out-projection (wo_sh reads are warp-uniform -> broadcast)
    float outv[8];
#pragma unroll
    for (int a = 0; a < 8; a++) outv[a] = 0.0f;
#pragma unroll
    for (int q = 0; q < 64; q++)
#pragma unroll
        for (int a = 0; a < 8; a++)
            outv[a] += ctx[q] * wo_sh[a*64 + q];

    const int gy = y0 + yy;
    const float dg = dispgap[b*NHW + gy*NW + x0 + x];
    const bool zero = (dg >= 2.0f);
#pragma unroll
    for (int a = 0; a < 8; a++)
        g_delta[((b*NCATT + a)*NH + gy)*NW + x0 + x] = zero ? 0.0f : outv[a];
}

// ---------------------------------------------------------------------------
// K3: broadcast add (FROZEN — 74% DRAM, at roofline).
// ---------------------------------------------------------------------------
__global__ void add_kernel(const float* __restrict__ attn, float* __restrict__ out) {
    int i4 = blockIdx.x * blockDim.x + threadIdx.x;
    float4 a = __ldcs(reinterpret_cast<const float4*>(attn) + i4);
    int inner = i4 & (NHW/4 - 1);
    int bad   = i4 >> 13;
    int ba    = bad / ND;
    float4 dl = __ldg(reinterpret_cast<const float4*>(g_delta) + ba*(NHW/4) + inner);
    a.x += dl.x; a.y += dl.y; a.z += dl.z; a.w += dl.w;
    __stcs(reinterpret_cast<float4*>(out) + i4, a);
}

// ---------------------------------------------------------------------------
extern "C" void kernel_launch(void* const* d_in, const int* in_sizes, int n_in,
                              void* d_out, int out_size) {
    const float* attn_vol = (const float*)d_in[0];
    const float* feat     = (const float*)d_in[1];
    const float* dispgap  = (const float*)d_in[2];
    const float* Wq       = (const float*)d_in[3];
    const float* Wk       = (const float*)d_in[4];
    const float* Wv       = (const float*)d_in[5];
    const float* Wo       = (const float*)d_in[6];
    float* out = (float*)d_out;

    const int smem2 = (2*SEG_F + NCATT*NEMB) * 4;   // 71680 B
    cudaFuncSetAttribute(qkv_mma_kernel,
                         cudaFuncAttributeMaxDynamicSharedMemorySize, SMEM1);
    cudaFuncSetAttribute(attn_kernel,
                         cudaFuncAttributeMaxDynamicSharedMemorySize, smem2);

    wfrag_kernel<<<1, 512>>>(Wq, Wk, Wv);
    qkv_mma_kernel<<<148, 512, SMEM1>>>(feat);
    attn_kernel<<<dim3(2, 64, NB), 256, smem2>>>(dispgap, Wo);
    add_kernel<<<(NB*NCATT*ND*NHW/4)/256, 256>>>(attn_vol, out);
}

// round 15
// speedup vs baseline: 3.9121x; 1.0741x over previous
#include <cuda_runtime.h>
#include <cstdint>

#define NB    4
#define NCATT 8
#define ND    48
#define NH    128
#define NW    256
#define NCF   80
#define NEMB  64
#define NHW   (NH*NW)          // 32768

// Scratch (device globals: allocation-free contract)
__device__ float g_Q[NB*NEMB*NHW];      // 33.5 MB
__device__ float g_K[NB*NEMB*NHW];
__device__ float g_V[NB*NEMB*NHW];
__device__ float g_delta[NB*NCATT*NHW]; // 16.8 MB
// fp16 weight fragments, m16n8k16 B-operand layout:
// u32 idx = ((s*24 + t)*32 + lane)*2 + j ; s<5, t<24
__device__ uint32_t g_WfragH[5*24*32*2];

__device__ __forceinline__ uint32_t smem_u32(const void* p) {
    uint32_t a;
    asm("{ .reg .u64 t; cvta.to.shared.u64 t, %1; cvt.u32.u64 %0, t; }"
        : "=r"(a) : "l"(p));
    return a;
}
// pack {lo, hi} floats -> f16x2 (first asm source lands in HIGH half)
__device__ __forceinline__ uint32_t pkh2(float lo, float hi) {
    uint32_t r;
    asm("cvt.rn.f16x2.f32 %0, %1, %2;" : "=r"(r) : "f"(hi), "f"(lo));
    return r;
}

// ---------------------------------------------------------------------------
// K0: fp16 B-operand fragment image for m16n8k16 (tiny, one block).
// thread map: n = t*8 + (l>>2); k = s*16 + (l&3)*2 + j*8, elements k, k+1.
// ---------------------------------------------------------------------------
__global__ void wfrag_kernel(const float* __restrict__ Wq,
                             const float* __restrict__ Wk,
                             const float* __restrict__ Wv) {
    for (int idx = threadIdx.x; idx < 5*24*32*2; idx += blockDim.x) {
        int j  = idx & 1;
        int pi = idx >> 1;
        int l  = pi & 31;
        int tt = pi >> 5;
        int t  = tt % 24, s = tt / 24;
        int e  = t*8 + (l >> 2);
        int k  = s*16 + (l & 3)*2 + j*8;     // 0..78, k+1 <= 79
        const float* W = (e < 64) ? (Wq + e*NCF)
                       : (e < 128) ? (Wk + (e-64)*NCF)
                                   : (Wv + (e-128)*NCF);
        g_WfragH[idx] = pkh2(W[k], W[k+1]);
    }
}

// ---------------------------------------------------------------------------
// K1: QKV projection via mma.sync m16n8k16 fp16 (full-rate legacy HMMA;
// tf32 m16n8k8 measured at rt~32/SMSP = slow path).  Persistent CTAs,
// resident B (30KB), double-buffered A.  fp16 eps == tf32 eps -> same accuracy.
// ---------------------------------------------------------------------------
#define APAD    132
#define A_FLOAT (80*APAD)          // floats per A buffer
#define A_BYTES (A_FLOAT*4)        // 42240
#define B_BYTES (5*24*32*2*4)      // 30720
#define SMEM1   (2*A_BYTES + B_BYTES)   // 115200
#define NTILES  (NB*256)           // 1024

__device__ __forceinline__ void mma_f16(float* c, const uint32_t* a,
                                        const uint32_t* b) {
    asm("mma.sync.aligned.m16n8k16.row.col.f32.f16.f16.f32 "
        "{%0,%1,%2,%3}, {%4,%5,%6,%7}, {%8,%9}, {%0,%1,%2,%3};"
        : "+f"(c[0]), "+f"(c[1]), "+f"(c[2]), "+f"(c[3])
        : "r"(a[0]), "r"(a[1]), "r"(a[2]), "r"(a[3]), "r"(b[0]), "r"(b[1]));
}
#define CPA16(dst, src) \
    asm volatile("cp.async.ca.shared.global [%0], [%1], 16;" \
                 :: "r"(dst), "l"(src))
#define CP_COMMIT() asm volatile("cp.async.commit_group;" ::: "memory")
#define CP_WAIT1()  asm volatile("cp.async.wait_group 1;" ::: "memory")
#define CP_WAIT0()  asm volatile("cp.async.wait_group 0;" ::: "memory")

__device__ __forceinline__ void a_load(uint32_t dstA, const float* __restrict__ feat,
                                       int tile, int tid) {
    const int b  = tile >> 8;
    const int n0 = (tile & 255) << 7;
    const float* srcA = feat + (size_t)b*NCF*NHW + n0;
#pragma unroll
    for (int i = 0; i < 5; i++) {                 // 2560 chunks / 512 thr
        const int idx = tid + i*512;
        const int k = idx >> 5, c = idx & 31;
        CPA16(dstA + (uint32_t)(k*APAD + c*4)*4, srcA + (size_t)k*NHW + c*4);
    }
}

__global__ __launch_bounds__(512, 1)
void qkv_mma_kernel(const float* __restrict__ feat) {
    extern __shared__ float sm[];
    float* shA[2] = { sm, sm + A_FLOAT };
    float* shB    = sm + 2*A_FLOAT;
    const int tid  = threadIdx.x;
    const int lane = tid & 31;
    const int wid  = tid >> 5;
    const uint32_t sbase = smem_u32(sm);
    const uint32_t aAddr[2] = { sbase, sbase + A_BYTES };

    // --- B resident load (once) + first A tile, one group ---
    {
        const uint32_t bb = sbase + 2*A_BYTES;
        const float4* srcB = reinterpret_cast<const float4*>(g_WfragH);
        for (int idx = tid; idx < B_BYTES/16; idx += 512)
            CPA16(bb + idx*16, srcB + idx);
        if ((int)blockIdx.x < NTILES)
            a_load(aAddr[0], feat, blockIdx.x, tid);
        CP_COMMIT();
    }

    const int pxg = wid & 7;            // 8 groups of 16 px
    const int eh  = wid >> 3;           // 2 e-halves of 96
    const int px0 = pxg*16;
    const int l4  = lane >> 2, lm4 = lane & 3;
    const float* bBase = shB + eh*12*64 + lane*2;

    int i = 0;
    for (int tile = blockIdx.x; tile < NTILES; tile += gridDim.x, i++) {
        const int cur = i & 1;
        const int nxt = cur ^ 1;
        __syncthreads();                 // everyone done reading shA[nxt]
        const int ntile = tile + gridDim.x;
        if (ntile < NTILES) a_load(aAddr[nxt], feat, ntile, tid);
        CP_COMMIT();
        CP_WAIT1();                      // A(tile) + B complete
        __syncthreads();

        const float* curA = shA[cur];
        float acc[12][4];
#pragma unroll
        for (int t = 0; t < 12; t++)
#pragma unroll
            for (int j = 0; j < 4; j++) acc[t][j] = 0.0f;

        const float* aCol = curA + px0 + l4;
#pragma unroll
        for (int s = 0; s < 5; s++) {
            // A fragment: px in {g, g+8}, k in {k0, k0+1, k0+8, k0+9}
            const float* ap = aCol + (s*16 + lm4*2)*APAD;
            float fa = ap[0],        fb = ap[APAD];
            float fc = ap[8],        fd = ap[APAD + 8];
            float fe = ap[8*APAD],   ff = ap[9*APAD];
            float fg = ap[8*APAD+8], fh = ap[9*APAD+8];
            uint32_t A[4];
            A[0] = pkh2(fa, fb);     // A[g][k0], A[g][k0+1]
            A[1] = pkh2(fc, fd);     // A[g+8][k0..]
            A[2] = pkh2(fe, ff);     // A[g][k0+8..]
            A[3] = pkh2(fg, fh);     // A[g+8][k0+8..]
            uint32_t B[12][2];
#pragma unroll
            for (int t = 0; t < 12; t++) {
                float2 bv = *reinterpret_cast<const float2*>(bBase + (s*24 + t)*64);
                B[t][0] = __float_as_uint(bv.x);
                B[t][1] = __float_as_uint(bv.y);
            }
#pragma unroll
            for (int t = 0; t < 12; t++)
                mma_f16(acc[t], A, B[t]);
        }

        const int b  = tile >> 8;
        const int n0 = (tile & 255) << 7;
#pragma unroll
        for (int t = 0; t < 12; t++) {
            const int e0 = (eh*12 + t)*8 + lm4*2;
            float* seg = (e0 < 64) ? g_Q : ((e0 < 128) ? g_K : g_V);
            const int ch0 = e0 & 63;
            float* d0 = seg + (size_t)(b*NEMB + ch0)*NHW + n0 + px0 + l4;
            float* d1 = d0 + NHW;
            d0[0] = acc[t][0];
            d1[0] = acc[t][1];
            d0[8] = acc[t][2];
            d1[8] = acc[t][3];
        }
    }
}

// ---------------------------------------------------------------------------
// K2: local windowed MHA (FROZEN from round 13).
// ---------------------------------------------------------------------------
#define SEG_CH   16
#define ROW_F    136                       // floats per smem row
#define SEG_F    (SEG_CH*4*ROW_F)          // 8704 floats = 34816 B
#define NCHUNK   (SEG_CH*4*34)             // 2176 16B chunks per segment

__device__ __forceinline__ void seg_load(float* buf, const float* __restrict__ src,
                                         int b, int e0, int y0, int x0, int tid) {
    const float* sb = src + (size_t)(b*NEMB + e0)*NHW;
#pragma unroll
    for (int i = 0; i < 9; i++) {
        const int idx = tid + i*256;
        if (i < 8 || idx < NCHUNK) {
            const int c34 = idx % 34;
            const int t4  = idx / 34;
            const int rr  = t4 & 3;
            const int ch  = t4 >> 2;
            const int gy  = y0 - 1 + rr;
            const int gxs = x0 - 4 + c34*4;
            float* d = buf + ch*544 + rr*ROW_F + c34*4;
            const bool ok = ((unsigned)gy < NH) & ((unsigned)gxs < (NW-3));
            if (ok) {
                const float* s = sb + (size_t)ch*NHW + (size_t)gy*NW + gxs;
                asm volatile("cp.async.ca.shared.global [%0], [%1], 16;"
                             :: "r"(smem_u32(d)), "l"(s));
            } else {
                *reinterpret_cast<float4*>(d) = make_float4(0.f,0.f,0.f,0.f);
            }
        }
    }
}

template<int E0>
__device__ __forceinline__ void score_seg(const float* sh, float (&sc)[36],
                                          const float (&Qr)[64], int bx) {
#pragma unroll
    for (int d = 0; d < 16; d++)
#pragma unroll
        for (int p = 0; p < 9; p++)
#pragma unroll
            for (int h = 0; h < 4; h++) {
                const int q = h*16 + d;
                const int L = p*64 + q;
                const int e = L/9, wi = L % 9;
                if (e >= E0 && e < E0 + SEG_CH) {
                    const int dyy = wi/3, dxx = wi % 3;
                    sc[h*9+p] += Qr[q] * sh[(e-E0)*544 + dyy*ROW_F + dxx + bx];
                }
            }
}

template<int E0>
__device__ __forceinline__ void ctx_seg(const float* sh, float (&ctx)[64],
                                        const float (&sc)[36], int bx) {
#pragma unroll
    for (int p = 0; p < 9; p++)
#pragma unroll
        for (int d = 0; d < 16; d++)
#pragma unroll
            for (int h = 0; h < 4; h++) {
                const int q = h*16 + d;
                const int L = p*64 + q;
                const int e = L/9, wi = L % 9;
                if (e >= E0 && e < E0 + SEG_CH) {
                    const int dyy = wi/3, dxx = wi % 3;
                    ctx[q] += sc[h*9+p] * sh[(e-E0)*544 + dyy*ROW_F + dxx + bx];
                }
            }
}

__global__ __launch_bounds__(256, 2)
void attn_kernel(const float* __restrict__ dispgap, const float* __restrict__ Wo) {
    extern __shared__ float smem2[];
    float* B0    = smem2;
    float* B1    = smem2 + SEG_F;
    float* wo_sh = smem2 + 2*SEG_F;
    const int b   = blockIdx.z;
    const int y0  = blockIdx.y * 2;
    const int x0  = blockIdx.x * 128;
    const int tid = threadIdx.x;
    const int x   = tid & 127;
    const int yy  = tid >> 7;
    const int bx  = yy*ROW_F + x + 4 - 1;      // col 3 maps to gx = x0-1

    for (int i = tid; i < NCATT*NEMB; i += 256) wo_sh[i] = Wo[i];

    seg_load(B0, g_K, b, 0,  y0, x0, tid);  CP_COMMIT();
    seg_load(B1, g_K, b, 16, y0, x0, tid);  CP_COMMIT();

    float Qr[64];
#pragma unroll
    for (int e = 0; e < 64; e++)
        Qr[e] = g_Q[(size_t)(b*NEMB + e)*NHW + (y0+yy)*NW + x0 + x];

    float sc[36];
#pragma unroll
    for (int i = 0; i < 36; i++) sc[i] = 0.0f;

    // seg 0
    CP_WAIT1(); __syncthreads();
    score_seg<0>(B0, sc, Qr, bx);
    __syncthreads();
    seg_load(B0, g_K, b, 32, y0, x0, tid);  CP_COMMIT();
    // seg 1
    CP_WAIT1(); __syncthreads();
    score_seg<16>(B1, sc, Qr, bx);
    __syncthreads();
    seg_load(B1, g_K, b, 48, y0, x0, tid);  CP_COMMIT();
    // seg 2
    CP_WAIT1(); __syncthreads();
    score_seg<32>(B0, sc, Qr, bx);
    __syncthreads();
    seg_load(B0, g_V, b, 0,  y0, x0, tid);  CP_COMMIT();
    // seg 3
    CP_WAIT1(); __syncthreads();
    score_seg<48>(B1, sc, Qr, bx);

    // softmax over p (SCALE = 0.25 folded in)
#pragma unroll
    for (int h = 0; h < 4; h++) {
        float m = sc[h*9];
#pragma unroll
        for (int p = 1; p < 9; p++) m = fmaxf(m, sc[h*9+p]);
        float s = 0.0f;
#pragma unroll
        for (int p = 0; p < 9; p++) {
            float ev = __expf(0.25f*(sc[h*9+p] - m));
            sc[h*9+p] = ev;
            s += ev;
        }
        float inv = __fdividef(1.0f, s);
#pragma unroll
        for (int p = 0; p < 9; p++) sc[h*9+p] *= inv;
    }
    __syncthreads();
    seg_load(B1, g_V, b, 16, y0, x0, tid);  CP_COMMIT();

    float ctx[64];
#pragma unroll
    for (int i = 0; i < 64; i++) ctx[i] = 0.0f;

    // seg 4
    CP_WAIT1(); __syncthreads();
    ctx_seg<0>(B0, ctx, sc, bx);
    __syncthreads();
    seg_load(B0, g_V, b, 32, y0, x0, tid);  CP_COMMIT();
    // seg 5
    CP_WAIT1(); __syncthreads();
    ctx_seg<16>(B1, ctx, sc, bx);
    __syncthreads();
    seg_load(B1, g_V, b, 48, y0, x0, tid);  CP_COMMIT();
    // seg 6
    CP_WAIT1(); __syncthreads();
    ctx_seg<32>(B0, ctx, sc, bx);
    // seg 7
    CP_WAIT0(); __syncthreads();
    ctx_seg<48>(B1, ctx, sc, bx);

    // out-projection (wo_sh reads are warp-uniform -> broadcast)
    float outv[8];
#pragma unroll
    for (int a = 0; a < 8; a++) outv[a] = 0.0f;
#pragma unroll
    for (int q = 0; q < 64; q++)
#pragma unroll
        for (int a = 0; a < 8; a++)
            outv[a] += ctx[q] * wo_sh[a*64 + q];

    const int gy = y0 + yy;
    const float dg = dispgap[b*NHW + gy*NW + x0 + x];
    const bool zero = (dg >= 2.0f);
#pragma unroll
    for (int a = 0; a < 8; a++)
        g_delta[((b*NCATT + a)*NH + gy)*NW + x0 + x] = zero ? 0.0f : outv[a];
}

// ---------------------------------------------------------------------------
// K3: broadcast add (FROZEN — at DRAM roofline).
// ---------------------------------------------------------------------------
__global__ void add_kernel(const float* __restrict__ attn, float* __restrict__ out) {
    int i4 = blockIdx.x * blockDim.x + threadIdx.x;
    float4 a = __ldcs(reinterpret_cast<const float4*>(attn) + i4);
    int inner = i4 & (NHW/4 - 1);
    int bad   = i4 >> 13;
    int ba    = bad / ND;
    float4 dl = __ldg(reinterpret_cast<const float4*>(g_delta) + ba*(NHW/4) + inner);
    a.x += dl.x; a.y += dl.y; a.z += dl.z; a.w += dl.w;
    __stcs(reinterpret_cast<float4*>(out) + i4, a);
}

// ---------------------------------------------------------------------------
extern "C" void kernel_launch(void* const* d_in, const int* in_sizes, int n_in,
                              void* d_out, int out_size) {
    const float* attn_vol = (const float*)d_in[0];
    const float* feat     = (const float*)d_in[1];
    const float* dispgap  = (const float*)d_in[2];
    const float* Wq       = (const float*)d_in[3];
    const float* Wk       = (const float*)d_in[4];
    const float* Wv       = (const float*)d_in[5];
    const float* Wo       = (const float*)d_in[6];
    float* out = (float*)d_out;

    const int smem2 = (2*SEG_F + NCATT*NEMB) * 4;   // 71680 B
    cudaFuncSetAttribute(qkv_mma_kernel,
                         cudaFuncAttributeMaxDynamicSharedMemorySize, SMEM1);
    cudaFuncSetAttribute(attn_kernel,
                         cudaFuncAttributeMaxDynamicSharedMemorySize, smem2);

    wfrag_kernel<<<1, 512>>>(Wq, Wk, Wv);
    qkv_mma_kernel<<<148, 512, SMEM1>>>(feat);
    attn_kernel<<<dim3(2, 64, NB), 256, smem2>>>(dispgap, Wo);
    add_kernel<<<(NB*NCATT*ND*NHW/4)/256, 256>>>(attn_vol, out);
}

// round 16
// speedup vs baseline: 4.2605x; 1.0891x over previous
#include <cuda_runtime.h>
#include <cstdint>

#define NB    4
#define NCATT 8
#define ND    48
#define NH    128
#define NW    256
#define NCF   80
#define NEMB  64
#define NHW   (NH*NW)          // 32768

// Scratch (device globals: allocation-free contract)
__device__ float g_Q[NB*NEMB*NHW];      // 33.5 MB
__device__ float g_K[NB*NEMB*NHW];
__device__ float g_V[NB*NEMB*NHW];
__device__ float g_delta[NB*NCATT*NHW]; // 16.8 MB
// fp16 weight fragments, m16n8k16 B-operand layout:
// u32 idx = ((s*24 + t)*32 + lane)*2 + j ; s<5, t<24
__device__ uint32_t g_WfragH[5*24*32*2];

__device__ __forceinline__ uint32_t smem_u32(const void* p) {
    uint32_t a;
    asm("{ .reg .u64 t; cvta.to.shared.u64 t, %1; cvt.u32.u64 %0, t; }"
        : "=r"(a) : "l"(p));
    return a;
}
// pack {lo, hi} floats -> f16x2 (first asm source lands in HIGH half)
__device__ __forceinline__ uint32_t pkh2(float lo, float hi) {
    uint32_t r;
    asm("cvt.rn.f16x2.f32 %0, %1, %2;" : "=r"(r) : "f"(hi), "f"(lo));
    return r;
}

// ---------------------------------------------------------------------------
// K0: fp16 B-operand fragment image for m16n8k16 (FROZEN).
// ---------------------------------------------------------------------------
__global__ void wfrag_kernel(const float* __restrict__ Wq,
                             const float* __restrict__ Wk,
                             const float* __restrict__ Wv) {
    for (int idx = threadIdx.x; idx < 5*24*32*2; idx += blockDim.x) {
        int j  = idx & 1;
        int pi = idx >> 1;
        int l  = pi & 31;
        int tt = pi >> 5;
        int t  = tt % 24, s = tt / 24;
        int e  = t*8 + (l >> 2);
        int k  = s*16 + (l & 3)*2 + j*8;     // 0..78, k+1 <= 79
        const float* W = (e < 64) ? (Wq + e*NCF)
                       : (e < 128) ? (Wk + (e-64)*NCF)
                                   : (Wv + (e-128)*NCF);
        g_WfragH[idx] = pkh2(W[k], W[k+1]);
    }
}

// ---------------------------------------------------------------------------
// K1: QKV projection via mma.sync m16n8k16 fp16 (FROZEN from round 15).
// ---------------------------------------------------------------------------
#define APAD    132
#define A_FLOAT (80*APAD)          // floats per A buffer
#define A_BYTES (A_FLOAT*4)        // 42240
#define B_BYTES (5*24*32*2*4)      // 30720
#define SMEM1   (2*A_BYTES + B_BYTES)   // 115200
#define NTILES  (NB*256)           // 1024

__device__ __forceinline__ void mma_f16(float* c, const uint32_t* a,
                                        const uint32_t* b) {
    asm("mma.sync.aligned.m16n8k16.row.col.f32.f16.f16.f32 "
        "{%0,%1,%2,%3}, {%4,%5,%6,%7}, {%8,%9}, {%0,%1,%2,%3};"
        : "+f"(c[0]), "+f"(c[1]), "+f"(c[2]), "+f"(c[3])
        : "r"(a[0]), "r"(a[1]), "r"(a[2]), "r"(a[3]), "r"(b[0]), "r"(b[1]));
}
#define CPA16(dst, src) \
    asm volatile("cp.async.ca.shared.global [%0], [%1], 16;" \
                 :: "r"(dst), "l"(src))
#define CP_COMMIT() asm volatile("cp.async.commit_group;" ::: "memory")
#define CP_WAIT1()  asm volatile("cp.async.wait_group 1;" ::: "memory")
#define CP_WAIT0()  asm volatile("cp.async.wait_group 0;" ::: "memory")

__device__ __forceinline__ void a_load(uint32_t dstA, const float* __restrict__ feat,
                                       int tile, int tid) {
    const int b  = tile >> 8;
    const int n0 = (tile & 255) << 7;
    const float* srcA = feat + (size_t)b*NCF*NHW + n0;
#pragma unroll
    for (int i = 0; i < 5; i++) {                 // 2560 chunks / 512 thr
        const int idx = tid + i*512;
        const int k = idx >> 5, c = idx & 31;
        CPA16(dstA + (uint32_t)(k*APAD + c*4)*4, srcA + (size_t)k*NHW + c*4);
    }
}

__global__ __launch_bounds__(512, 1)
void qkv_mma_kernel(const float* __restrict__ feat) {
    extern __shared__ float sm[];
    float* shA[2] = { sm, sm + A_FLOAT };
    float* shB    = sm + 2*A_FLOAT;
    const int tid  = threadIdx.x;
    const int lane = tid & 31;
    const int wid  = tid >> 5;
    const uint32_t sbase = smem_u32(sm);
    const uint32_t aAddr[2] = { sbase, sbase + A_BYTES };

    {
        const uint32_t bb = sbase + 2*A_BYTES;
        const float4* srcB = reinterpret_cast<const float4*>(g_WfragH);
        for (int idx = tid; idx < B_BYTES/16; idx += 512)
            CPA16(bb + idx*16, srcB + idx);
        if ((int)blockIdx.x < NTILES)
            a_load(aAddr[0], feat, blockIdx.x, tid);
        CP_COMMIT();
    }

    const int pxg = wid & 7;            // 8 groups of 16 px
    const int eh  = wid >> 3;           // 2 e-halves of 96
    const int px0 = pxg*16;
    const int l4  = lane >> 2, lm4 = lane & 3;
    const float* bBase = shB + eh*12*64 + lane*2;

    int i = 0;
    for (int tile = blockIdx.x; tile < NTILES; tile += gridDim.x, i++) {
        const int cur = i & 1;
        const int nxt = cur ^ 1;
        __syncthreads();
        const int ntile = tile + gridDim.x;
        if (ntile < NTILES) a_load(aAddr[nxt], feat, ntile, tid);
        CP_COMMIT();
        CP_WAIT1();
        __syncthreads();

        const float* curA = shA[cur];
        float acc[12][4];
#pragma unroll
        for (int t = 0; t < 12; t++)
#pragma unroll
            for (int j = 0; j < 4; j++) acc[t][j] = 0.0f;

        const float* aCol = curA + px0 + l4;
#pragma unroll
        for (int s = 0; s < 5; s++) {
            const float* ap = aCol + (s*16 + lm4*2)*APAD;
            float fa = ap[0],        fb = ap[APAD];
            float fc = ap[8],        fd = ap[APAD + 8];
            float fe = ap[8*APAD],   ff = ap[9*APAD];
            float fg = ap[8*APAD+8], fh = ap[9*APAD+8];
            uint32_t A[4];
            A[0] = pkh2(fa, fb);
            A[1] = pkh2(fc, fd);
            A[2] = pkh2(fe, ff);
            A[3] = pkh2(fg, fh);
            uint32_t B[12][2];
#pragma unroll
            for (int t = 0; t < 12; t++) {
                float2 bv = *reinterpret_cast<const float2*>(bBase + (s*24 + t)*64);
                B[t][0] = __float_as_uint(bv.x);
                B[t][1] = __float_as_uint(bv.y);
            }
#pragma unroll
            for (int t = 0; t < 12; t++)
                mma_f16(acc[t], A, B[t]);
        }

        const int b  = tile >> 8;
        const int n0 = (tile & 255) << 7;
#pragma unroll
        for (int t = 0; t < 12; t++) {
            const int e0 = (eh*12 + t)*8 + lm4*2;
            float* seg = (e0 < 64) ? g_Q : ((e0 < 128) ? g_K : g_V);
            const int ch0 = e0 & 63;
            float* d0 = seg + (size_t)(b*NEMB + ch0)*NHW + n0 + px0 + l4;
            float* d1 = d0 + NHW;
            d0[0] = acc[t][0];
            d1[0] = acc[t][1];
            d0[8] = acc[t][2];
            d1[8] = acc[t][3];
        }
    }
}

// ---------------------------------------------------------------------------
// K2: local windowed MHA — retiled to 4 y-rows x 64 px per 256-thr block.
// Tile = 6 rows x 72 px per 16-ch segment (halo traffic/px: 1.088 -> 0.864 KB).
// Same 8-segment double-buffered cp.async pipeline and mixed-mapping math.
// ---------------------------------------------------------------------------
#define SEG_CH   16
#define TROWS    6
#define ROW_F    72                        // floats per smem row
#define CH_STR   (TROWS*ROW_F)             // 432 floats per channel
#define SEG_F    (SEG_CH*CH_STR)           // 6912 floats = 27648 B
#define NCHUNK   (SEG_CH*TROWS*18)         // 1728 16B chunks per segment

__device__ __forceinline__ void seg_load(float* buf, const float* __restrict__ src,
                                         int b, int e0, int y0, int x0, int tid) {
    const float* sb = src + (size_t)(b*NEMB + e0)*NHW;
#pragma unroll
    for (int i = 0; i < 7; i++) {
        const int idx = tid + i*256;
        if (i < 6 || idx < NCHUNK) {
            const int c18 = idx % 18;
            const int t6  = idx / 18;
            const int rr  = t6 % 6;
            const int ch  = t6 / 6;
            const int gy  = y0 - 1 + rr;
            const int gxs = x0 - 4 + c18*4;
            float* d = buf + ch*CH_STR + rr*ROW_F + c18*4;
            const bool ok = ((unsigned)gy < NH) & ((unsigned)gxs < (NW-3));
            if (ok) {
                const float* s = sb + (size_t)ch*NHW + (size_t)gy*NW + gxs;
                asm volatile("cp.async.ca.shared.global [%0], [%1], 16;"
                             :: "r"(smem_u32(d)), "l"(s));
            } else {
                *reinterpret_cast<float4*>(d) = make_float4(0.f,0.f,0.f,0.f);
            }
        }
    }
}

template<int E0>
__device__ __forceinline__ void score_seg(const float* sh, float (&sc)[36],
                                          const float (&Qr)[64], int bx) {
#pragma unroll
    for (int d = 0; d < 16; d++)
#pragma unroll
        for (int p = 0; p < 9; p++)
#pragma unroll
            for (int h = 0; h < 4; h++) {
                const int q = h*16 + d;
                const int L = p*64 + q;
                const int e = L/9, wi = L % 9;
                if (e >= E0 && e < E0 + SEG_CH) {
                    const int dyy = wi/3, dxx = wi % 3;
                    sc[h*9+p] += Qr[q] * sh[(e-E0)*CH_STR + dyy*ROW_F + dxx + bx];
                }
            }
}

template<int E0>
__device__ __forceinline__ void ctx_seg(const float* sh, float (&ctx)[64],
                                        const float (&sc)[36], int bx) {
#pragma unroll
    for (int p = 0; p < 9; p++)
#pragma unroll
        for (int d = 0; d < 16; d++)
#pragma unroll
            for (int h = 0; h < 4; h++) {
                const int q = h*16 + d;
                const int L = p*64 + q;
                const int e = L/9, wi = L % 9;
                if (e >= E0 && e < E0 + SEG_CH) {
                    const int dyy = wi/3, dxx = wi % 3;
                    ctx[q] += sc[h*9+p] * sh[(e-E0)*CH_STR + dyy*ROW_F + dxx + bx];
                }
            }
}

__global__ __launch_bounds__(256, 2)
void attn_kernel(const float* __restrict__ dispgap, const float* __restrict__ Wo) {
    extern __shared__ float smem2[];
    float* B0    = smem2;
    float* B1    = smem2 + SEG_F;
    float* wo_sh = smem2 + 2*SEG_F;
    const int b   = blockIdx.z;
    const int y0  = blockIdx.y * 4;
    const int x0  = blockIdx.x * 64;
    const int tid = threadIdx.x;
    const int x   = tid & 63;
    const int yy  = tid >> 6;                  // 0..3
    const int bx  = yy*ROW_F + x + 3;          // dxx=0 -> gx = x0 + x - 1

    for (int i = tid; i < NCATT*NEMB; i += 256) wo_sh[i] = Wo[i];

    seg_load(B0, g_K, b, 0,  y0, x0, tid);  CP_COMMIT();
    seg_load(B1, g_K, b, 16, y0, x0, tid);  CP_COMMIT();

    float Qr[64];
#pragma unroll
    for (int e = 0; e < 64; e++)
        Qr[e] = g_Q[(size_t)(b*NEMB + e)*NHW + (y0+yy)*NW + x0 + x];

    float sc[36];
#pragma unroll
    for (int i = 0; i < 36; i++) sc[i] = 0.0f;

    // seg 0
    CP_WAIT1(); __syncthreads();
    score_seg<0>(B0, sc, Qr, bx);
    __syncthreads();
    seg_load(B0, g_K, b, 32, y0, x0, tid);  CP_COMMIT();
    // seg 1
    CP_WAIT1(); __syncthreads();
    score_seg<16>(B1, sc, Qr, bx);
    __syncthreads();
    seg_load(B1, g_K, b, 48, y0, x0, tid);  CP_COMMIT();
    // seg 2
    CP_WAIT1(); __syncthreads();
    score_seg<32>(B0, sc, Qr, bx);
    __syncthreads();
    seg_load(B0, g_V, b, 0,  y0, x0, tid);  CP_COMMIT();
    // seg 3
    CP_WAIT1(); __syncthreads();
    score_seg<48>(B1, sc, Qr, bx);

    // softmax over p (SCALE = 0.25 folded in)
#pragma unroll
    for (int h = 0; h < 4; h++) {
        float m = sc[h*9];
#pragma unroll
        for (int p = 1; p < 9; p++) m = fmaxf(m, sc[h*9+p]);
        float s = 0.0f;
#pragma unroll
        for (int p = 0; p < 9; p++) {
            float ev = __expf(0.25f*(sc[h*9+p] - m));
            sc[h*9+p] = ev;
            s += ev;
        }
        float inv = __fdividef(1.0f, s);
#pragma unroll
        for (int p = 0; p < 9; p++) sc[h*9+p] *= inv;
    }
    __syncthreads();
    seg_load(B1, g_V, b, 16, y0, x0, tid);  CP_COMMIT();

    float ctx[64];
#pragma unroll
    for (int i = 0; i < 64; i++) ctx[i] = 0.0f;

    // seg 4
    CP_WAIT1(); __syncthreads();
    ctx_seg<0>(B0, ctx, sc, bx);
    __syncthreads();
    seg_load(B0, g_V, b, 32, y0, x0, tid);  CP_COMMIT();
    // seg 5
    CP_WAIT1(); __syncthreads();
    ctx_seg<16>(B1, ctx, sc, bx);
    __syncthreads();
    seg_load(B1, g_V, b, 48, y0, x0, tid);  CP_COMMIT();
    // seg 6
    CP_WAIT1(); __syncthreads();
    ctx_seg<32>(B0, ctx, sc, bx);
    // seg 7
    CP_WAIT0(); __syncthreads();
    ctx_seg<48>(B1, ctx, sc, bx);

    // out-projection (wo_sh reads are warp-uniform -> broadcast)
    float outv[8];
#pragma unroll
    for (int a = 0; a < 8; a++) outv[a] = 0.0f;
#pragma unroll
    for (int q = 0; q < 64; q++)
#pragma unroll
        for (int a = 0; a < 8; a++)
            outv[a] += ctx[q] * wo_sh[a*64 + q];

    const int gy = y0 + yy;
    const float dg = dispgap[b*NHW + gy*NW + x0 + x];
    const bool zero = (dg >= 2.0f);
#pragma unroll
    for (int a = 0; a < 8; a++)
        g_delta[((b*NCATT + a)*NH + gy)*NW + x0 + x] = zero ? 0.0f : outv[a];
}

// ---------------------------------------------------------------------------
// K3: broadcast add — 4 float4s per thread (grid-stride) for deeper MLP and
// 4x fewer blocks.
// ---------------------------------------------------------------------------
#define TOT4     (NB*NCATT*ND*NHW/4)       // 12582912
#define K3J      4
#define K3STRIDE (TOT4/K3J)                // 3145728

__global__ void add_kernel(const float* __restrict__ attn, float* __restrict__ out) {
    const int gid = blockIdx.x * blockDim.x + threadIdx.x;
#pragma unroll
    for (int j = 0; j < K3J; j++) {
        const int i4 = gid + j*K3STRIDE;
        float4 a = __ldcs(reinterpret_cast<const float4*>(attn) + i4);
        const int inner = i4 & (NHW/4 - 1);
        const int ba    = (i4 >> 13) / ND;
        float4 dl = __ldg(reinterpret_cast<const float4*>(g_delta) + ba*(NHW/4) + inner);
        a.x += dl.x; a.y += dl.y; a.z += dl.z; a.w += dl.w;
        __stcs(reinterpret_cast<float4*>(out) + i4, a);
    }
}

// ---------------------------------------------------------------------------
extern "C" void kernel_launch(void* const* d_in, const int* in_sizes, int n_in,
                              void* d_out, int out_size) {
    const float* attn_vol = (const float*)d_in[0];
    const float* feat     = (const float*)d_in[1];
    const float* dispgap  = (const float*)d_in[2];
    const float* Wq       = (const float*)d_in[3];
    const float* Wk       = (const float*)d_in[4];
    const float* Wv       = (const float*)d_in[5];
    const float* Wo       = (const float*)d_in[6];
    float* out = (float*)d_out;

    const int smem2 = (2*SEG_F + NCATT*NEMB) * 4;   // 55296 + 2048 = 57344 B
    cudaFuncSetAttribute(qkv_mma_kernel,
                         cudaFuncAttributeMaxDynamicSharedMemorySize, SMEM1);
    cudaFuncSetAttribute(attn_kernel,
                         cudaFuncAttributeMaxDynamicSharedMemorySize, smem2);

    wfrag_kernel<<<1, 512>>>(Wq, Wk, Wv);
    qkv_mma_kernel<<<148, 512, SMEM1>>>(feat);
    attn_kernel<<<dim3(NW/64, NH/4, NB), 256, smem2>>>(dispgap, Wo);
    add_kernel<<<K3STRIDE/256, 256>>>(attn_vol, out);
}